// round 1
// baseline (speedup 1.0000x reference)
#include <cuda_runtime.h>
#include <cuda_bf16.h>
#include <cstdint>

// Problem constants
#define NN0 100000
#define NN1 25000
#define NN2 6250
#define EE0 600000
#define EE1 150000
#define EE2 37500
#define KCH 6

// ---------------- Scratch (device globals; no allocation allowed) ----------------
__device__ __align__(16) float g_T [(size_t)NN1 * 768];      // T storage: level0 [N0,18], level1 [N1,768], level2 [N2,768]
__device__ __align__(16) float g_h0[(size_t)NN0 * 128];
__device__ __align__(16) float g_P [(size_t)NN1 * 128];      // pooled features (reused)
__device__ __align__(16) float g_h1[(size_t)NN1 * 128];
__device__ __align__(16) float g_h2[(size_t)NN2 * 256];
__device__ __align__(16) float g_w [EE0];
__device__ __align__(16) float g_dinv[NN0];

// ---------------- Utility kernels ----------------
__global__ void zero_kernel(float* __restrict__ p, int n) {
    int i = blockIdx.x * blockDim.x + threadIdx.x;
    if (i < n) p[i] = 0.0f;
}

__global__ void deg_kernel(const int* __restrict__ src, float* __restrict__ deg, int E) {
    int e = blockIdx.x * blockDim.x + threadIdx.x;
    if (e < E) atomicAdd(&deg[src[e]], 1.0f);
}

__global__ void dinv_kernel(float* __restrict__ d, int n) {
    int i = blockIdx.x * blockDim.x + threadIdx.x;
    if (i < n) {
        float v = d[i];
        d[i] = (v > 0.0f) ? rsqrtf(fmaxf(v, 1.0f)) : 0.0f;
    }
}

__global__ void edgew_kernel(const int* __restrict__ src, const int* __restrict__ dst,
                             const float* __restrict__ dinv, float* __restrict__ w, int E) {
    int e = blockIdx.x * blockDim.x + threadIdx.x;
    if (e < E) w[e] = -(dinv[src[e]] * dinv[dst[e]]);
}

// out[i*os+f] = zero ? 0 : alpha*in[i*is+f]
__global__ void scale_copy_kernel(const float* __restrict__ in, int is,
                                  float* __restrict__ out, int os,
                                  int N, int F, float alpha, int zero) {
    int tid = blockIdx.x * blockDim.x + threadIdx.x;
    if (tid >= N * F) return;
    int i = tid / F, f = tid - i * F;
    float v = 0.0f;
    if (!zero) v = alpha * in[(size_t)i * is + f];
    out[(size_t)i * os + f] = v;
}

// ---------------- Propagation (scatter-add) ----------------
// F small (level0 F=3): one thread per (edge, feature)
__global__ void prop_scalar_kernel(const int* __restrict__ src, const int* __restrict__ dst,
                                   const float* __restrict__ w,
                                   const float* __restrict__ in, float* __restrict__ out,
                                   int E, int F, int stride, float scale) {
    int tid = blockIdx.x * blockDim.x + threadIdx.x;
    if (tid >= E * F) return;
    int e = tid / F, f = tid - e * F;
    float c = scale * w[e];
    atomicAdd(&out[(size_t)dst[e] * stride + f], c * in[(size_t)src[e] * stride + f]);
}

// F=128: 32 threads/edge, float4 gather, 4 scalar atomics
__global__ void prop_vec4_kernel(const int* __restrict__ src, const int* __restrict__ dst,
                                 const float* __restrict__ w,
                                 const float* __restrict__ in, float* __restrict__ out,
                                 int E, int stride, float scale) {
    int gid = blockIdx.x * blockDim.x + threadIdx.x;
    int e = gid >> 5;
    if (e >= E) return;
    int f = (gid & 31) * 4;
    int s = src[e], d = dst[e];
    float c = scale * w[e];
    float4 v = *reinterpret_cast<const float4*>(&in[(size_t)s * stride + f]);
    float* o = &out[(size_t)d * stride + f];
    atomicAdd(o + 0, c * v.x);
    atomicAdd(o + 1, c * v.y);
    atomicAdd(o + 2, c * v.z);
    atomicAdd(o + 3, c * v.w);
}

// ---------------- Level-0 output: h0 = T[N0,18] @ W0[18,128] + b0 ----------------
__global__ void level0_out_kernel(const float* __restrict__ T, const float* __restrict__ W,
                                  const float* __restrict__ b, float* __restrict__ h0, int N) {
    int half = threadIdx.x >> 7;           // 0 or 1 (2 nodes per 256-thread block)
    int node = blockIdx.x * 2 + half;
    int j = threadIdx.x & 127;
    __shared__ float sT[2][18];
    if (j < 18 && node < N) sT[half][j] = T[(size_t)node * 18 + j];
    __syncthreads();
    if (node >= N) return;
    float s = b[j];
#pragma unroll
    for (int t = 0; t < 18; t++) s = fmaf(sT[half][t], W[t * 128 + j], s);
    h0[(size_t)node * 128 + j] = s;
}

// ---------------- Pool: out[rows[e],:] += vals[e]*relu(in[cols[e],:]) (F=128) ----------------
__global__ void pool_kernel(const int* __restrict__ rows, const int* __restrict__ cols,
                            const float* __restrict__ vals,
                            const float* __restrict__ in, float* __restrict__ out,
                            int E, int do_relu) {
    int gid = blockIdx.x * blockDim.x + threadIdx.x;
    int e = gid >> 5;
    if (e >= E) return;
    int f = (gid & 31) * 4;
    float v = vals[e];
    float4 x = *reinterpret_cast<const float4*>(&in[(size_t)cols[e] * 128 + f]);
    if (do_relu) {
        x.x = fmaxf(x.x, 0.0f); x.y = fmaxf(x.y, 0.0f);
        x.z = fmaxf(x.z, 0.0f); x.w = fmaxf(x.w, 0.0f);
    }
    float* o = &out[(size_t)rows[e] * 128 + f];
    atomicAdd(o + 0, v * x.x);
    atomicAdd(o + 1, v * x.y);
    atomicAdd(o + 2, v * x.z);
    atomicAdd(o + 3, v * x.w);
}

// ---------------- GEMM: C[M,N] = A[M,K]@B[K,N] + bias[N] ----------------
// 64x64 tile, BK=16, 256 threads, 4x4 microtile. N multiple of 64, K multiple of 16.
__global__ void gemm_bias_kernel(const float* __restrict__ A, const float* __restrict__ B,
                                 const float* __restrict__ bias, float* __restrict__ C,
                                 int M, int N, int K) {
    __shared__ __align__(16) float As[16][64];
    __shared__ __align__(16) float Bs[16][64];
    int row0 = blockIdx.y * 64, col0 = blockIdx.x * 64;
    int tid = threadIdx.x;
    int tx = tid & 15, ty = tid >> 4;
    int aRow = tid >> 2;              // 0..63
    int aK   = (tid & 3) * 4;         // 0..12
    int bK   = tid >> 4;              // 0..15
    int bN   = (tid & 15) * 4;        // 0..60
    float acc[4][4] = {};
    for (int k0 = 0; k0 < K; k0 += 16) {
        float4 av = make_float4(0, 0, 0, 0);
        int gr = row0 + aRow;
        if (gr < M) av = *reinterpret_cast<const float4*>(&A[(size_t)gr * K + k0 + aK]);
        As[aK + 0][aRow] = av.x; As[aK + 1][aRow] = av.y;
        As[aK + 2][aRow] = av.z; As[aK + 3][aRow] = av.w;
        float4 bv = *reinterpret_cast<const float4*>(&B[(size_t)(k0 + bK) * N + col0 + bN]);
        *reinterpret_cast<float4*>(&Bs[bK][bN]) = bv;
        __syncthreads();
#pragma unroll
        for (int k = 0; k < 16; k++) {
            float4 a4 = *reinterpret_cast<const float4*>(&As[k][ty * 4]);
            float4 b4 = *reinterpret_cast<const float4*>(&Bs[k][tx * 4]);
            float ar[4] = {a4.x, a4.y, a4.z, a4.w};
            float br[4] = {b4.x, b4.y, b4.z, b4.w};
#pragma unroll
            for (int i = 0; i < 4; i++)
#pragma unroll
                for (int j = 0; j < 4; j++)
                    acc[i][j] = fmaf(ar[i], br[j], acc[i][j]);
        }
        __syncthreads();
    }
#pragma unroll
    for (int i = 0; i < 4; i++) {
        int r = row0 + ty * 4 + i;
        if (r < M) {
            int c = col0 + tx * 4;
            float4 o;
            o.x = acc[i][0] + bias[c + 0];
            o.y = acc[i][1] + bias[c + 1];
            o.z = acc[i][2] + bias[c + 2];
            o.w = acc[i][3] + bias[c + 3];
            *reinterpret_cast<float4*>(&C[(size_t)r * N + c]) = o;
        }
    }
}

// ---------------- Final: Z = linW[10, 1600000] @ h2 + linb ----------------
__global__ void init_out_kernel(const float* __restrict__ linb, float* __restrict__ out) {
    int i = threadIdx.x;
    if (i < 10) out[i] = linb[i];
}

__global__ void final_kernel(const float* __restrict__ linW, const float* __restrict__ h,
                             float* __restrict__ out) {
    const int VL4 = (NN2 * 256) / 4;  // 400000 float4s
    float acc[10];
#pragma unroll
    for (int j = 0; j < 10; j++) acc[j] = 0.0f;
    const float4* h4 = reinterpret_cast<const float4*>(h);
    for (int i = blockIdx.x * blockDim.x + threadIdx.x; i < VL4; i += gridDim.x * blockDim.x) {
        float4 hv = h4[i];
#pragma unroll
        for (int j = 0; j < 10; j++) {
            float4 wv = reinterpret_cast<const float4*>(linW + (size_t)j * (NN2 * 256))[i];
            acc[j] += wv.x * hv.x + wv.y * hv.y + wv.z * hv.z + wv.w * hv.w;
        }
    }
    __shared__ float red[256];
#pragma unroll
    for (int j = 0; j < 10; j++) {
        red[threadIdx.x] = acc[j];
        __syncthreads();
        for (int s = 128; s > 0; s >>= 1) {
            if (threadIdx.x < (unsigned)s) red[threadIdx.x] += red[threadIdx.x + s];
            __syncthreads();
        }
        if (threadIdx.x == 0) atomicAdd(&out[j], red[0]);
        __syncthreads();
    }
}

// ---------------- Host-side driver ----------------
static inline int cdiv(int a, int b) { return (a + b - 1) / b; }

static void launch_prop(const int* src, const int* dst, const float* w,
                        const float* in, float* out, int E, int Fin, int stride, float scale) {
    if (Fin == 3) {
        int n = E * 3;
        prop_scalar_kernel<<<cdiv(n, 256), 256>>>(src, dst, w, in, out, E, 3, stride, scale);
    } else {
        int n = E * 32;
        prop_vec4_kernel<<<cdiv(n, 256), 256>>>(src, dst, w, in, out, E, stride, scale);
    }
}

static void run_cheb(const int* ei, int E, int Nn, int Fin, int Fout,
                     const float* X, const float* W, const float* b,
                     float* Tbuf, float* outbuf, float* dinv, float* w) {
    const int* src = ei;
    const int* dst = ei + E;
    int stride = KCH * Fin;
    int nf = Nn * Fin;

    zero_kernel<<<cdiv(Nn, 256), 256>>>(dinv, Nn);
    deg_kernel<<<cdiv(E, 256), 256>>>(src, dinv, E);
    dinv_kernel<<<cdiv(Nn, 256), 256>>>(dinv, Nn);
    edgew_kernel<<<cdiv(E, 256), 256>>>(src, dst, dinv, w, E);

    // T0 = X
    scale_copy_kernel<<<cdiv(nf, 256), 256>>>(X, Fin, Tbuf, stride, Nn, Fin, 1.0f, 0);
    // T1 = prop(T0)
    scale_copy_kernel<<<cdiv(nf, 256), 256>>>(Tbuf, stride, Tbuf + Fin, stride, Nn, Fin, 0.0f, 1);
    launch_prop(src, dst, w, Tbuf, Tbuf + Fin, E, Fin, stride, 1.0f);
    // Tk = 2*prop(T_{k-1}) - T_{k-2}
    for (int k = 2; k < KCH; k++) {
        scale_copy_kernel<<<cdiv(nf, 256), 256>>>(Tbuf + (size_t)(k - 2) * Fin, stride,
                                                  Tbuf + (size_t)k * Fin, stride,
                                                  Nn, Fin, -1.0f, 0);
        launch_prop(src, dst, w, Tbuf + (size_t)(k - 1) * Fin, Tbuf + (size_t)k * Fin,
                    E, Fin, stride, 2.0f);
    }
    // out = [T0|...|T5] @ Wflat + b
    if (Fin == 3) {
        level0_out_kernel<<<cdiv(Nn, 2), 256>>>(Tbuf, W, b, outbuf, Nn);
    } else {
        dim3 grid(Fout / 64, cdiv(Nn, 64));
        gemm_bias_kernel<<<grid, 256>>>(Tbuf, W, b, outbuf, Nn, Fout, stride);
    }
}

extern "C" void kernel_launch(void* const* d_in, const int* in_sizes, int n_in,
                              void* d_out, int out_size) {
    const float* x      = (const float*)d_in[0];
    const int*   ei0    = (const int*)d_in[1];
    const int*   ei1    = (const int*)d_in[2];
    const int*   ei2    = (const int*)d_in[3];
    const float* W0     = (const float*)d_in[4];
    const float* b0     = (const float*)d_in[5];
    const float* W1     = (const float*)d_in[6];
    const float* b1     = (const float*)d_in[7];
    const float* W2     = (const float*)d_in[8];
    const float* b2     = (const float*)d_in[9];
    const int*   D0r    = (const int*)d_in[10];
    const int*   D0c    = (const int*)d_in[11];
    const float* D0v    = (const float*)d_in[12];
    const int*   D1r    = (const int*)d_in[13];
    const int*   D1c    = (const int*)d_in[14];
    const float* D1v    = (const float*)d_in[15];
    const float* linW   = (const float*)d_in[16];
    const float* linb   = (const float*)d_in[17];
    float* out = (float*)d_out;

    float *T, *h0, *P, *h1, *h2, *w, *dinv;
    cudaGetSymbolAddress((void**)&T,    g_T);
    cudaGetSymbolAddress((void**)&h0,   g_h0);
    cudaGetSymbolAddress((void**)&P,    g_P);
    cudaGetSymbolAddress((void**)&h1,   g_h1);
    cudaGetSymbolAddress((void**)&h2,   g_h2);
    cudaGetSymbolAddress((void**)&w,    g_w);
    cudaGetSymbolAddress((void**)&dinv, g_dinv);

    // Level 0: ChebConv(3 -> 128) on N0
    run_cheb(ei0, EE0, NN0, 3, 128, x, W0, b0, T, h0, dinv, w);

    // Pool 0 (fused ReLU): [N0,128] -> [N1,128]
    zero_kernel<<<cdiv(NN1 * 128, 256), 256>>>(P, NN1 * 128);
    pool_kernel<<<cdiv(100000 * 32, 256), 256>>>(D0r, D0c, D0v, h0, P, 100000, 1);

    // Level 1: ChebConv(128 -> 128) on N1
    run_cheb(ei1, EE1, NN1, 128, 128, P, W1, b1, T, h1, dinv, w);

    // Pool 1 (fused ReLU): [N1,128] -> [N2,128]
    zero_kernel<<<cdiv(NN2 * 128, 256), 256>>>(P, NN2 * 128);
    pool_kernel<<<cdiv(25000 * 32, 256), 256>>>(D1r, D1c, D1v, h1, P, 25000, 1);

    // Level 2: ChebConv(128 -> 256) on N2 (no relu)
    run_cheb(ei2, EE2, NN2, 128, 256, P, W2, b2, T, h2, dinv, w);

    // Final: Z = linW @ vec(h2) + linb
    init_out_kernel<<<1, 32>>>(linb, out);
    final_kernel<<<1024, 256>>>(linW, h2, out);
}

// round 3
// speedup vs baseline: 1.3386x; 1.3386x over previous
#include <cuda_runtime.h>
#include <cuda_bf16.h>
#include <cstdint>

// Problem constants
#define NN0 100000
#define NN1 25000
#define NN2 6250
#define EE0 600000
#define EE1 150000
#define EE2 37500
#define KCH 6

// ---------------- Scratch (device globals; no allocation allowed) ----------------
__device__ __align__(16) float g_T [(size_t)NN1 * 768];      // T storage: level0 [N0,18], level1 [N1,768], level2 [N2,768]
__device__ __align__(16) float g_h0[(size_t)NN0 * 128];
__device__ __align__(16) float g_P [(size_t)NN1 * 128];      // pooled features (reused)
__device__ __align__(16) float g_h1[(size_t)NN1 * 128];
__device__ __align__(16) float g_h2[(size_t)NN2 * 256];
__device__ __align__(16) float g_w [EE0];
__device__ __align__(16) float g_dinv[NN0];

// Vector reduction: one 16B red.global instead of 4 scalar atomics.
__device__ __forceinline__ void red_add_v4(float* addr, float a, float b, float c, float d) {
    asm volatile("red.global.add.v4.f32 [%0], {%1,%2,%3,%4};"
                 :: "l"(addr), "f"(a), "f"(b), "f"(c), "f"(d) : "memory");
}

// ---------------- Utility kernels ----------------
__global__ void zero_kernel(float* __restrict__ p, int n) {
    int i = blockIdx.x * blockDim.x + threadIdx.x;
    if (i < n) p[i] = 0.0f;
}

__global__ void deg_kernel(const int* __restrict__ src, float* __restrict__ deg, int E) {
    int e = blockIdx.x * blockDim.x + threadIdx.x;
    if (e < E) atomicAdd(&deg[src[e]], 1.0f);
}

__global__ void dinv_kernel(float* __restrict__ d, int n) {
    int i = blockIdx.x * blockDim.x + threadIdx.x;
    if (i < n) {
        float v = d[i];
        d[i] = (v > 0.0f) ? rsqrtf(fmaxf(v, 1.0f)) : 0.0f;
    }
}

__global__ void edgew_kernel(const int* __restrict__ src, const int* __restrict__ dst,
                             const float* __restrict__ dinv, float* __restrict__ w, int E) {
    int e = blockIdx.x * blockDim.x + threadIdx.x;
    if (e < E) w[e] = -(dinv[src[e]] * dinv[dst[e]]);
}

// out[i*os+f] = zero ? 0 : alpha*in[i*is+f]
__global__ void scale_copy_kernel(const float* __restrict__ in, int is,
                                  float* __restrict__ out, int os,
                                  int N, int F, float alpha, int zero) {
    int tid = blockIdx.x * blockDim.x + threadIdx.x;
    if (tid >= N * F) return;
    int i = tid / F, f = tid - i * F;
    float v = 0.0f;
    if (!zero) v = alpha * in[(size_t)i * is + f];
    out[(size_t)i * os + f] = v;
}

// ---------------- Propagation (scatter-add) ----------------
// F small (level0 F=3): one thread per (edge, feature)
__global__ void prop_scalar_kernel(const int* __restrict__ src, const int* __restrict__ dst,
                                   const float* __restrict__ w,
                                   const float* __restrict__ in, float* __restrict__ out,
                                   int E, int F, int stride, float scale) {
    int tid = blockIdx.x * blockDim.x + threadIdx.x;
    if (tid >= E * F) return;
    int e = tid / F, f = tid - e * F;
    float c = scale * w[e];
    atomicAdd(&out[(size_t)dst[e] * stride + f], c * in[(size_t)src[e] * stride + f]);
}

// F=128: 32 threads/edge (one warp per edge), float4 gather, vector red scatter
__global__ void prop_vec4_kernel(const int* __restrict__ src, const int* __restrict__ dst,
                                 const float* __restrict__ w,
                                 const float* __restrict__ in, float* __restrict__ out,
                                 int E, int stride, float scale) {
    int gid = blockIdx.x * blockDim.x + threadIdx.x;
    int e = gid >> 5;
    if (e >= E) return;
    int f = (gid & 31) * 4;
    int s = __ldg(&src[e]), d = __ldg(&dst[e]);
    float c = scale * __ldg(&w[e]);
    float4 v = *reinterpret_cast<const float4*>(&in[(size_t)s * stride + f]);
    red_add_v4(&out[(size_t)d * stride + f], c * v.x, c * v.y, c * v.z, c * v.w);
}

// ---------------- Level-0 output: h0 = T[N0,18] @ W0[18,128] + b0 ----------------
__global__ void level0_out_kernel(const float* __restrict__ T, const float* __restrict__ W,
                                  const float* __restrict__ b, float* __restrict__ h0, int N) {
    int half = threadIdx.x >> 7;           // 0 or 1 (2 nodes per 256-thread block)
    int node = blockIdx.x * 2 + half;
    int j = threadIdx.x & 127;
    __shared__ float sT[2][18];
    if (j < 18 && node < N) sT[half][j] = T[(size_t)node * 18 + j];
    __syncthreads();
    if (node >= N) return;
    float s = b[j];
#pragma unroll
    for (int t = 0; t < 18; t++) s = fmaf(sT[half][t], W[t * 128 + j], s);
    h0[(size_t)node * 128 + j] = s;
}

// ---------------- Pool: out[rows[e],:] += vals[e]*relu(in[cols[e],:]) (F=128) ----------------
__global__ void pool_kernel(const int* __restrict__ rows, const int* __restrict__ cols,
                            const float* __restrict__ vals,
                            const float* __restrict__ in, float* __restrict__ out,
                            int E, int do_relu) {
    int gid = blockIdx.x * blockDim.x + threadIdx.x;
    int e = gid >> 5;
    if (e >= E) return;
    int f = (gid & 31) * 4;
    float v = __ldg(&vals[e]);
    float4 x = *reinterpret_cast<const float4*>(&in[(size_t)__ldg(&cols[e]) * 128 + f]);
    if (do_relu) {
        x.x = fmaxf(x.x, 0.0f); x.y = fmaxf(x.y, 0.0f);
        x.z = fmaxf(x.z, 0.0f); x.w = fmaxf(x.w, 0.0f);
    }
    red_add_v4(&out[(size_t)__ldg(&rows[e]) * 128 + f], v * x.x, v * x.y, v * x.z, v * x.w);
}

// ---------------- GEMM: C[M,N] = A[M,K]@B[K,N] + bias[N] ----------------
// 128x64 tile, BK=16, 256 threads, 8x4 microtile. N multiple of 64, K multiple of 16.
__global__ __launch_bounds__(256) void gemm_bias_kernel(
        const float* __restrict__ A, const float* __restrict__ B,
        const float* __restrict__ bias, float* __restrict__ C,
        int M, int N, int K) {
    __shared__ __align__(16) float As[16][128];
    __shared__ __align__(16) float Bs[16][64];
    int row0 = blockIdx.y * 128, col0 = blockIdx.x * 64;
    int tid = threadIdx.x;
    int tx = tid & 15;           // 0..15 : column group (4 cols)
    int ty = tid >> 4;           // 0..15 : row group (8 rows)
    int bK = tid >> 4;           // 0..15
    int bN = (tid & 15) * 4;     // 0..60
    float acc[8][4] = {};
    for (int k0 = 0; k0 < K; k0 += 16) {
        // Load A tile: 128 rows x 16 k = 512 float4, 2 per thread
#pragma unroll
        for (int l = 0; l < 2; l++) {
            int idx = tid + l * 256;
            int aRow = idx >> 2;          // 0..127
            int aK = (idx & 3) * 4;       // 0,4,8,12
            float4 av = make_float4(0, 0, 0, 0);
            int gr = row0 + aRow;
            if (gr < M) av = *reinterpret_cast<const float4*>(&A[(size_t)gr * K + k0 + aK]);
            As[aK + 0][aRow] = av.x; As[aK + 1][aRow] = av.y;
            As[aK + 2][aRow] = av.z; As[aK + 3][aRow] = av.w;
        }
        // Load B tile: 16 k x 64 n = 256 float4, 1 per thread
        float4 bv = *reinterpret_cast<const float4*>(&B[(size_t)(k0 + bK) * N + col0 + bN]);
        *reinterpret_cast<float4*>(&Bs[bK][bN]) = bv;
        __syncthreads();
#pragma unroll
        for (int k = 0; k < 16; k++) {
            float4 a0 = *reinterpret_cast<const float4*>(&As[k][ty * 8]);
            float4 a1 = *reinterpret_cast<const float4*>(&As[k][ty * 8 + 4]);
            float4 b4 = *reinterpret_cast<const float4*>(&Bs[k][tx * 4]);
            float ar[8] = {a0.x, a0.y, a0.z, a0.w, a1.x, a1.y, a1.z, a1.w};
            float br[4] = {b4.x, b4.y, b4.z, b4.w};
#pragma unroll
            for (int i = 0; i < 8; i++)
#pragma unroll
                for (int j = 0; j < 4; j++)
                    acc[i][j] = fmaf(ar[i], br[j], acc[i][j]);
        }
        __syncthreads();
    }
    int c = col0 + tx * 4;
    float4 bb = *reinterpret_cast<const float4*>(&bias[c]);
#pragma unroll
    for (int i = 0; i < 8; i++) {
        int r = row0 + ty * 8 + i;
        if (r < M) {
            float4 o;
            o.x = acc[i][0] + bb.x;
            o.y = acc[i][1] + bb.y;
            o.z = acc[i][2] + bb.z;
            o.w = acc[i][3] + bb.w;
            *reinterpret_cast<float4*>(&C[(size_t)r * N + c]) = o;
        }
    }
}

// ---------------- Final: Z = linW[10, 1600000] @ h2 + linb ----------------
__global__ void init_out_kernel(const float* __restrict__ linb, float* __restrict__ out) {
    int i = threadIdx.x;
    if (i < 10) out[i] = linb[i];
}

__global__ void final_kernel(const float* __restrict__ linW, const float* __restrict__ h,
                             float* __restrict__ out) {
    const int VL4 = (NN2 * 256) / 4;  // 400000 float4s
    float acc[10];
#pragma unroll
    for (int j = 0; j < 10; j++) acc[j] = 0.0f;
    const float4* h4 = reinterpret_cast<const float4*>(h);
    for (int i = blockIdx.x * blockDim.x + threadIdx.x; i < VL4; i += gridDim.x * blockDim.x) {
        float4 hv = h4[i];
#pragma unroll
        for (int j = 0; j < 10; j++) {
            float4 wv = reinterpret_cast<const float4*>(linW + (size_t)j * (NN2 * 256))[i];
            acc[j] += wv.x * hv.x + wv.y * hv.y + wv.z * hv.z + wv.w * hv.w;
        }
    }
    __shared__ float red[256];
#pragma unroll
    for (int j = 0; j < 10; j++) {
        red[threadIdx.x] = acc[j];
        __syncthreads();
        for (int s = 128; s > 0; s >>= 1) {
            if (threadIdx.x < (unsigned)s) red[threadIdx.x] += red[threadIdx.x + s];
            __syncthreads();
        }
        if (threadIdx.x == 0) atomicAdd(&out[j], red[0]);
        __syncthreads();
    }
}

// ---------------- Host-side driver ----------------
static inline int cdiv(int a, int b) { return (a + b - 1) / b; }

static void launch_prop(const int* src, const int* dst, const float* w,
                        const float* in, float* out, int E, int Fin, int stride, float scale) {
    if (Fin == 3) {
        int n = E * 3;
        prop_scalar_kernel<<<cdiv(n, 256), 256>>>(src, dst, w, in, out, E, 3, stride, scale);
    } else {
        int n = E * 32;
        prop_vec4_kernel<<<cdiv(n, 256), 256>>>(src, dst, w, in, out, E, stride, scale);
    }
}

static void run_cheb(const int* ei, int E, int Nn, int Fin, int Fout,
                     const float* X, const float* W, const float* b,
                     float* Tbuf, float* outbuf, float* dinv, float* w) {
    const int* src = ei;
    const int* dst = ei + E;
    int stride = KCH * Fin;
    int nf = Nn * Fin;

    zero_kernel<<<cdiv(Nn, 256), 256>>>(dinv, Nn);
    deg_kernel<<<cdiv(E, 256), 256>>>(src, dinv, E);
    dinv_kernel<<<cdiv(Nn, 256), 256>>>(dinv, Nn);
    edgew_kernel<<<cdiv(E, 256), 256>>>(src, dst, dinv, w, E);

    // T0 = X
    scale_copy_kernel<<<cdiv(nf, 256), 256>>>(X, Fin, Tbuf, stride, Nn, Fin, 1.0f, 0);
    // T1 = prop(T0)
    scale_copy_kernel<<<cdiv(nf, 256), 256>>>(Tbuf, stride, Tbuf + Fin, stride, Nn, Fin, 0.0f, 1);
    launch_prop(src, dst, w, Tbuf, Tbuf + Fin, E, Fin, stride, 1.0f);
    // Tk = 2*prop(T_{k-1}) - T_{k-2}
    for (int k = 2; k < KCH; k++) {
        scale_copy_kernel<<<cdiv(nf, 256), 256>>>(Tbuf + (size_t)(k - 2) * Fin, stride,
                                                  Tbuf + (size_t)k * Fin, stride,
                                                  Nn, Fin, -1.0f, 0);
        launch_prop(src, dst, w, Tbuf + (size_t)(k - 1) * Fin, Tbuf + (size_t)k * Fin,
                    E, Fin, stride, 2.0f);
    }
    // out = [T0|...|T5] @ Wflat + b
    if (Fin == 3) {
        level0_out_kernel<<<cdiv(Nn, 2), 256>>>(Tbuf, W, b, outbuf, Nn);
    } else {
        dim3 grid(Fout / 64, cdiv(Nn, 128));
        gemm_bias_kernel<<<grid, 256>>>(Tbuf, W, b, outbuf, Nn, Fout, stride);
    }
}

extern "C" void kernel_launch(void* const* d_in, const int* in_sizes, int n_in,
                              void* d_out, int out_size) {
    const float* x      = (const float*)d_in[0];
    const int*   ei0    = (const int*)d_in[1];
    const int*   ei1    = (const int*)d_in[2];
    const int*   ei2    = (const int*)d_in[3];
    const float* W0     = (const float*)d_in[4];
    const float* b0     = (const float*)d_in[5];
    const float* W1     = (const float*)d_in[6];
    const float* b1     = (const float*)d_in[7];
    const float* W2     = (const float*)d_in[8];
    const float* b2     = (const float*)d_in[9];
    const int*   D0r    = (const int*)d_in[10];
    const int*   D0c    = (const int*)d_in[11];
    const float* D0v    = (const float*)d_in[12];
    const int*   D1r    = (const int*)d_in[13];
    const int*   D1c    = (const int*)d_in[14];
    const float* D1v    = (const float*)d_in[15];
    const float* linW   = (const float*)d_in[16];
    const float* linb   = (const float*)d_in[17];
    float* out = (float*)d_out;

    float *T, *h0, *P, *h1, *h2, *w, *dinv;
    cudaGetSymbolAddress((void**)&T,    g_T);
    cudaGetSymbolAddress((void**)&h0,   g_h0);
    cudaGetSymbolAddress((void**)&P,    g_P);
    cudaGetSymbolAddress((void**)&h1,   g_h1);
    cudaGetSymbolAddress((void**)&h2,   g_h2);
    cudaGetSymbolAddress((void**)&w,    g_w);
    cudaGetSymbolAddress((void**)&dinv, g_dinv);

    // Level 0: ChebConv(3 -> 128) on N0
    run_cheb(ei0, EE0, NN0, 3, 128, x, W0, b0, T, h0, dinv, w);

    // Pool 0 (fused ReLU): [N0,128] -> [N1,128]
    zero_kernel<<<cdiv(NN1 * 128, 256), 256>>>(P, NN1 * 128);
    pool_kernel<<<cdiv(100000 * 32, 256), 256>>>(D0r, D0c, D0v, h0, P, 100000, 1);

    // Level 1: ChebConv(128 -> 128) on N1
    run_cheb(ei1, EE1, NN1, 128, 128, P, W1, b1, T, h1, dinv, w);

    // Pool 1 (fused ReLU): [N1,128] -> [N2,128]
    zero_kernel<<<cdiv(NN2 * 128, 256), 256>>>(P, NN2 * 128);
    pool_kernel<<<cdiv(25000 * 32, 256), 256>>>(D1r, D1c, D1v, h1, P, 25000, 1);

    // Level 2: ChebConv(128 -> 256) on N2 (no relu)
    run_cheb(ei2, EE2, NN2, 128, 256, P, W2, b2, T, h2, dinv, w);

    // Final: Z = linW @ vec(h2) + linb
    init_out_kernel<<<1, 32>>>(linb, out);
    final_kernel<<<1024, 256>>>(linW, h2, out);
}

// round 5
// speedup vs baseline: 1.6178x; 1.2085x over previous
#include <cuda_runtime.h>
#include <cuda_bf16.h>
#include <cstdint>

// Problem constants
#define NN0 100000
#define NN1 25000
#define NN2 6250
#define EE0 600000
#define EE1 150000
#define EE2 37500
#define KCH 6

// ---------------- Scratch (device globals; no allocation allowed) ----------------
__device__ __align__(16) float g_T [(size_t)NN1 * 768];      // T storage: level0 [N0,18], level1 [N1,768], level2 [N2,768]
__device__ __align__(16) float g_h0[(size_t)NN0 * 128];
__device__ __align__(16) float g_P [(size_t)NN1 * 128];      // pooled features (reused)
__device__ __align__(16) float g_h1[(size_t)NN1 * 128];
__device__ __align__(16) float g_h2[(size_t)NN2 * 256];
__device__ __align__(16) float g_w [EE0];
__device__ __align__(16) float g_dinv[NN0];

// Vector reduction: one 16B red.global instead of 4 scalar atomics.
__device__ __forceinline__ void red_add_v4(float* addr, float a, float b, float c, float d) {
    asm volatile("red.global.add.v4.f32 [%0], {%1,%2,%3,%4};"
                 :: "l"(addr), "f"(a), "f"(b), "f"(c), "f"(d) : "memory");
}

__device__ __forceinline__ uint32_t sm_u32(const void* p) {
    uint32_t r;
    asm("{.reg .u64 t; cvta.to.shared.u64 t, %1; cvt.u32.u64 %0, t;}" : "=r"(r) : "l"(p));
    return r;
}

// ---------------- Utility kernels ----------------
__global__ void zero_kernel(float* __restrict__ p, int n) {
    int i = blockIdx.x * blockDim.x + threadIdx.x;
    if (i < n) p[i] = 0.0f;
}

__global__ void deg_kernel(const int* __restrict__ src, float* __restrict__ deg, int E) {
    int e = blockIdx.x * blockDim.x + threadIdx.x;
    if (e < E) atomicAdd(&deg[src[e]], 1.0f);
}

__global__ void dinv_kernel(float* __restrict__ d, int n) {
    int i = blockIdx.x * blockDim.x + threadIdx.x;
    if (i < n) {
        float v = d[i];
        d[i] = (v > 0.0f) ? rsqrtf(fmaxf(v, 1.0f)) : 0.0f;
    }
}

__global__ void edgew_kernel(const int* __restrict__ src, const int* __restrict__ dst,
                             const float* __restrict__ dinv, float* __restrict__ w, int E) {
    int e = blockIdx.x * blockDim.x + threadIdx.x;
    if (e < E) w[e] = -(dinv[src[e]] * dinv[dst[e]]);
}

// out[i*os+f] = zero ? 0 : alpha*in[i*is+f]
__global__ void scale_copy_kernel(const float* __restrict__ in, int is,
                                  float* __restrict__ out, int os,
                                  int N, int F, float alpha, int zero) {
    int tid = blockIdx.x * blockDim.x + threadIdx.x;
    if (tid >= N * F) return;
    int i = tid / F, f = tid - i * F;
    float v = 0.0f;
    if (!zero) v = alpha * in[(size_t)i * is + f];
    out[(size_t)i * os + f] = v;
}

// ---------------- Propagation (scatter-add) ----------------
__global__ void prop_scalar_kernel(const int* __restrict__ src, const int* __restrict__ dst,
                                   const float* __restrict__ w,
                                   const float* __restrict__ in, float* __restrict__ out,
                                   int E, int F, int stride, float scale) {
    int tid = blockIdx.x * blockDim.x + threadIdx.x;
    if (tid >= E * F) return;
    int e = tid / F, f = tid - e * F;
    float c = scale * w[e];
    atomicAdd(&out[(size_t)dst[e] * stride + f], c * in[(size_t)src[e] * stride + f]);
}

// F=128: 32 threads/edge (one warp per edge), float4 gather, vector red scatter
__global__ void prop_vec4_kernel(const int* __restrict__ src, const int* __restrict__ dst,
                                 const float* __restrict__ w,
                                 const float* __restrict__ in, float* __restrict__ out,
                                 int E, int stride, float scale) {
    int gid = blockIdx.x * blockDim.x + threadIdx.x;
    int e = gid >> 5;
    if (e >= E) return;
    int f = (gid & 31) * 4;
    int s = __ldg(&src[e]), d = __ldg(&dst[e]);
    float c = scale * __ldg(&w[e]);
    float4 v = *reinterpret_cast<const float4*>(&in[(size_t)s * stride + f]);
    red_add_v4(&out[(size_t)d * stride + f], c * v.x, c * v.y, c * v.z, c * v.w);
}

// ---------------- Level-0 output: h0 = T[N0,18] @ W0[18,128] + b0 ----------------
__global__ void level0_out_kernel(const float* __restrict__ T, const float* __restrict__ W,
                                  const float* __restrict__ b, float* __restrict__ h0, int N) {
    int half = threadIdx.x >> 7;
    int node = blockIdx.x * 2 + half;
    int j = threadIdx.x & 127;
    __shared__ float sT[2][18];
    if (j < 18 && node < N) sT[half][j] = T[(size_t)node * 18 + j];
    __syncthreads();
    if (node >= N) return;
    float s = b[j];
#pragma unroll
    for (int t = 0; t < 18; t++) s = fmaf(sT[half][t], W[t * 128 + j], s);
    h0[(size_t)node * 128 + j] = s;
}

// ---------------- Pool ----------------
__global__ void pool_kernel(const int* __restrict__ rows, const int* __restrict__ cols,
                            const float* __restrict__ vals,
                            const float* __restrict__ in, float* __restrict__ out,
                            int E, int do_relu) {
    int gid = blockIdx.x * blockDim.x + threadIdx.x;
    int e = gid >> 5;
    if (e >= E) return;
    int f = (gid & 31) * 4;
    float v = __ldg(&vals[e]);
    float4 x = *reinterpret_cast<const float4*>(&in[(size_t)__ldg(&cols[e]) * 128 + f]);
    if (do_relu) {
        x.x = fmaxf(x.x, 0.0f); x.y = fmaxf(x.y, 0.0f);
        x.z = fmaxf(x.z, 0.0f); x.w = fmaxf(x.w, 0.0f);
    }
    red_add_v4(&out[(size_t)__ldg(&rows[e]) * 128 + f], v * x.x, v * x.y, v * x.z, v * x.w);
}

// ---------------- Tensor-core GEMM (bf16 3-term split, fp32 accum) ----------------
// C[M,N] = A[M,K] @ B[K,N] + bias[N], internally A,B split hi/lo bf16:
//   C ~= Ahi@Bhi + Ahi@Blo + Alo@Bhi    (error ~ eps_bf16^2 ~ 6e-5, well under 1e-3)
// Block tile 128(M) x 64(N), BK=32. 8 warps: 4(M) x 2(N), warp tile 32x32.
// K multiple of 32, N multiple of 64.
#define APAD 8
#define BPAD 8
__global__ __launch_bounds__(256) void gemm_bias_tc_kernel(
        const float* __restrict__ A, const float* __restrict__ B,
        const float* __restrict__ bias, float* __restrict__ C,
        int M, int N, int K) {
    __shared__ __nv_bfloat16 Ahi[128][32 + APAD];
    __shared__ __nv_bfloat16 Alo[128][32 + APAD];
    __shared__ __nv_bfloat16 Bhi[32][64 + BPAD];
    __shared__ __nv_bfloat16 Blo[32][64 + BPAD];

    const int tid = threadIdx.x;
    const int lane = tid & 31;
    const int warp = tid >> 5;
    const int wm = warp & 3;          // 0..3 : warp row (32 M each)
    const int wn = warp >> 2;         // 0..1 : warp col (32 N each)
    const int row0 = blockIdx.y * 128;
    const int col0 = blockIdx.x * 64;

    float acc[2][4][4];
#pragma unroll
    for (int i = 0; i < 2; i++)
#pragma unroll
        for (int j = 0; j < 4; j++)
#pragma unroll
            for (int v = 0; v < 4; v++) acc[i][j][v] = 0.0f;

    for (int k0 = 0; k0 < K; k0 += 32) {
        // ---- Load + split A tile: 128 x 32 fp32 = 1024 float4, 4 per thread
#pragma unroll
        for (int l = 0; l < 4; l++) {
            int idx = tid + l * 256;
            int r = idx >> 3;
            int kk = (idx & 7) * 4;
            float4 av = make_float4(0, 0, 0, 0);
            int gr = row0 + r;
            if (gr < M) av = *reinterpret_cast<const float4*>(&A[(size_t)gr * K + k0 + kk]);
            __nv_bfloat16 h0 = __float2bfloat16_rn(av.x);
            __nv_bfloat16 h1 = __float2bfloat16_rn(av.y);
            __nv_bfloat16 h2 = __float2bfloat16_rn(av.z);
            __nv_bfloat16 h3 = __float2bfloat16_rn(av.w);
            __nv_bfloat16 l0 = __float2bfloat16_rn(av.x - __bfloat162float(h0));
            __nv_bfloat16 l1 = __float2bfloat16_rn(av.y - __bfloat162float(h1));
            __nv_bfloat16 l2 = __float2bfloat16_rn(av.z - __bfloat162float(h2));
            __nv_bfloat16 l3 = __float2bfloat16_rn(av.w - __bfloat162float(h3));
            Ahi[r][kk + 0] = h0; Ahi[r][kk + 1] = h1; Ahi[r][kk + 2] = h2; Ahi[r][kk + 3] = h3;
            Alo[r][kk + 0] = l0; Alo[r][kk + 1] = l1; Alo[r][kk + 2] = l2; Alo[r][kk + 3] = l3;
        }
        // ---- Load + split B tile: 32 x 64 fp32 = 512 float4, 2 per thread
#pragma unroll
        for (int l = 0; l < 2; l++) {
            int idx = tid + l * 256;
            int r = idx >> 4;
            int nn = (idx & 15) * 4;
            float4 bv = *reinterpret_cast<const float4*>(&B[(size_t)(k0 + r) * N + col0 + nn]);
            __nv_bfloat16 h0 = __float2bfloat16_rn(bv.x);
            __nv_bfloat16 h1 = __float2bfloat16_rn(bv.y);
            __nv_bfloat16 h2 = __float2bfloat16_rn(bv.z);
            __nv_bfloat16 h3 = __float2bfloat16_rn(bv.w);
            __nv_bfloat16 l0 = __float2bfloat16_rn(bv.x - __bfloat162float(h0));
            __nv_bfloat16 l1 = __float2bfloat16_rn(bv.y - __bfloat162float(h1));
            __nv_bfloat16 l2 = __float2bfloat16_rn(bv.z - __bfloat162float(h2));
            __nv_bfloat16 l3 = __float2bfloat16_rn(bv.w - __bfloat162float(h3));
            Bhi[r][nn + 0] = h0; Bhi[r][nn + 1] = h1; Bhi[r][nn + 2] = h2; Bhi[r][nn + 3] = h3;
            Blo[r][nn + 0] = l0; Blo[r][nn + 1] = l1; Blo[r][nn + 2] = l2; Blo[r][nn + 3] = l3;
        }
        __syncthreads();

        // ---- Compute: 2 k16 steps
#pragma unroll
        for (int ks = 0; ks < 32; ks += 16) {
            // A fragments (2 m16 frags), hi and lo
            uint32_t ah[2][4], al[2][4];
#pragma unroll
            for (int mf = 0; mf < 2; mf++) {
                int ar = wm * 32 + mf * 16 + (lane & 15);
                int ac = ks + (lane >> 4) * 8;
                uint32_t addr_h = sm_u32(&Ahi[ar][ac]);
                asm volatile("ldmatrix.sync.aligned.m8n8.x4.shared.b16 {%0,%1,%2,%3}, [%4];"
                             : "=r"(ah[mf][0]), "=r"(ah[mf][1]), "=r"(ah[mf][2]), "=r"(ah[mf][3])
                             : "r"(addr_h));
                uint32_t addr_l = sm_u32(&Alo[ar][ac]);
                asm volatile("ldmatrix.sync.aligned.m8n8.x4.shared.b16 {%0,%1,%2,%3}, [%4];"
                             : "=r"(al[mf][0]), "=r"(al[mf][1]), "=r"(al[mf][2]), "=r"(al[mf][3])
                             : "r"(addr_l));
            }
            // B fragments: 2 pairs of n8 tiles (x4.trans covers n16)
#pragma unroll
            for (int p = 0; p < 2; p++) {
                int bk = ks + (lane & 15);
                int bn = wn * 32 + p * 16 + (lane >> 4) * 8;
                uint32_t bh[4], bl[4];
                uint32_t addr_h = sm_u32(&Bhi[bk][bn]);
                asm volatile("ldmatrix.sync.aligned.m8n8.x4.trans.shared.b16 {%0,%1,%2,%3}, [%4];"
                             : "=r"(bh[0]), "=r"(bh[1]), "=r"(bh[2]), "=r"(bh[3])
                             : "r"(addr_h));
                uint32_t addr_l = sm_u32(&Blo[bk][bn]);
                asm volatile("ldmatrix.sync.aligned.m8n8.x4.trans.shared.b16 {%0,%1,%2,%3}, [%4];"
                             : "=r"(bl[0]), "=r"(bl[1]), "=r"(bl[2]), "=r"(bl[3])
                             : "r"(addr_l));
#pragma unroll
                for (int mf = 0; mf < 2; mf++) {
#pragma unroll
                    for (int q = 0; q < 2; q++) {
                        int nf = p * 2 + q;
                        float* c = acc[mf][nf];
                        // Ahi @ Bhi
                        asm volatile(
                            "mma.sync.aligned.m16n8k16.row.col.f32.bf16.bf16.f32 "
                            "{%0,%1,%2,%3}, {%4,%5,%6,%7}, {%8,%9}, {%0,%1,%2,%3};"
                            : "+f"(c[0]), "+f"(c[1]), "+f"(c[2]), "+f"(c[3])
                            : "r"(ah[mf][0]), "r"(ah[mf][1]), "r"(ah[mf][2]), "r"(ah[mf][3]),
                              "r"(bh[2 * q]), "r"(bh[2 * q + 1]));
                        // Ahi @ Blo
                        asm volatile(
                            "mma.sync.aligned.m16n8k16.row.col.f32.bf16.bf16.f32 "
                            "{%0,%1,%2,%3}, {%4,%5,%6,%7}, {%8,%9}, {%0,%1,%2,%3};"
                            : "+f"(c[0]), "+f"(c[1]), "+f"(c[2]), "+f"(c[3])
                            : "r"(ah[mf][0]), "r"(ah[mf][1]), "r"(ah[mf][2]), "r"(ah[mf][3]),
                              "r"(bl[2 * q]), "r"(bl[2 * q + 1]));
                        // Alo @ Bhi
                        asm volatile(
                            "mma.sync.aligned.m16n8k16.row.col.f32.bf16.bf16.f32 "
                            "{%0,%1,%2,%3}, {%4,%5,%6,%7}, {%8,%9}, {%0,%1,%2,%3};"
                            : "+f"(c[0]), "+f"(c[1]), "+f"(c[2]), "+f"(c[3])
                            : "r"(al[mf][0]), "r"(al[mf][1]), "r"(al[mf][2]), "r"(al[mf][3]),
                              "r"(bh[2 * q]), "r"(bh[2 * q + 1]));
                    }
                }
            }
        }
        __syncthreads();
    }

    // ---- Epilogue: bias + store (fp32)
#pragma unroll
    for (int mf = 0; mf < 2; mf++) {
#pragma unroll
        for (int nf = 0; nf < 4; nf++) {
            int col = col0 + wn * 32 + nf * 8 + (lane & 3) * 2;
            float bx = bias[col], by = bias[col + 1];
            int r0 = row0 + wm * 32 + mf * 16 + (lane >> 2);
            if (r0 < M) {
                float2 o = make_float2(acc[mf][nf][0] + bx, acc[mf][nf][1] + by);
                *reinterpret_cast<float2*>(&C[(size_t)r0 * N + col]) = o;
            }
            int r1 = r0 + 8;
            if (r1 < M) {
                float2 o = make_float2(acc[mf][nf][2] + bx, acc[mf][nf][3] + by);
                *reinterpret_cast<float2*>(&C[(size_t)r1 * N + col]) = o;
            }
        }
    }
}

// ---------------- Final: Z = linW[10, 1600000] @ h2 + linb ----------------
__global__ void init_out_kernel(const float* __restrict__ linb, float* __restrict__ out) {
    int i = threadIdx.x;
    if (i < 10) out[i] = linb[i];
}

__global__ void final_kernel(const float* __restrict__ linW, const float* __restrict__ h,
                             float* __restrict__ out) {
    const int VL4 = (NN2 * 256) / 4;
    float acc[10];
#pragma unroll
    for (int j = 0; j < 10; j++) acc[j] = 0.0f;
    const float4* h4 = reinterpret_cast<const float4*>(h);
    for (int i = blockIdx.x * blockDim.x + threadIdx.x; i < VL4; i += gridDim.x * blockDim.x) {
        float4 hv = h4[i];
#pragma unroll
        for (int j = 0; j < 10; j++) {
            float4 wv = reinterpret_cast<const float4*>(linW + (size_t)j * (NN2 * 256))[i];
            acc[j] += wv.x * hv.x + wv.y * hv.y + wv.z * hv.z + wv.w * hv.w;
        }
    }
    __shared__ float red[256];
#pragma unroll
    for (int j = 0; j < 10; j++) {
        red[threadIdx.x] = acc[j];
        __syncthreads();
        for (int s = 128; s > 0; s >>= 1) {
            if (threadIdx.x < (unsigned)s) red[threadIdx.x] += red[threadIdx.x + s];
            __syncthreads();
        }
        if (threadIdx.x == 0) atomicAdd(&out[j], red[0]);
        __syncthreads();
    }
}

// ---------------- Host-side driver ----------------
static inline int cdiv(int a, int b) { return (a + b - 1) / b; }

static void launch_prop(const int* src, const int* dst, const float* w,
                        const float* in, float* out, int E, int Fin, int stride, float scale) {
    if (Fin == 3) {
        int n = E * 3;
        prop_scalar_kernel<<<cdiv(n, 256), 256>>>(src, dst, w, in, out, E, 3, stride, scale);
    } else {
        int n = E * 32;
        prop_vec4_kernel<<<cdiv(n, 256), 256>>>(src, dst, w, in, out, E, stride, scale);
    }
}

static void run_cheb(const int* ei, int E, int Nn, int Fin, int Fout,
                     const float* X, const float* W, const float* b,
                     float* Tbuf, float* outbuf, float* dinv, float* w) {
    const int* src = ei;
    const int* dst = ei + E;
    int stride = KCH * Fin;
    int nf = Nn * Fin;

    zero_kernel<<<cdiv(Nn, 256), 256>>>(dinv, Nn);
    deg_kernel<<<cdiv(E, 256), 256>>>(src, dinv, E);
    dinv_kernel<<<cdiv(Nn, 256), 256>>>(dinv, Nn);
    edgew_kernel<<<cdiv(E, 256), 256>>>(src, dst, dinv, w, E);

    // T0 = X
    scale_copy_kernel<<<cdiv(nf, 256), 256>>>(X, Fin, Tbuf, stride, Nn, Fin, 1.0f, 0);
    // T1 = prop(T0)
    scale_copy_kernel<<<cdiv(nf, 256), 256>>>(Tbuf, stride, Tbuf + Fin, stride, Nn, Fin, 0.0f, 1);
    launch_prop(src, dst, w, Tbuf, Tbuf + Fin, E, Fin, stride, 1.0f);
    // Tk = 2*prop(T_{k-1}) - T_{k-2}
    for (int k = 2; k < KCH; k++) {
        scale_copy_kernel<<<cdiv(nf, 256), 256>>>(Tbuf + (size_t)(k - 2) * Fin, stride,
                                                  Tbuf + (size_t)k * Fin, stride,
                                                  Nn, Fin, -1.0f, 0);
        launch_prop(src, dst, w, Tbuf + (size_t)(k - 1) * Fin, Tbuf + (size_t)k * Fin,
                    E, Fin, stride, 2.0f);
    }
    // out = [T0|...|T5] @ Wflat + b
    if (Fin == 3) {
        level0_out_kernel<<<cdiv(Nn, 2), 256>>>(Tbuf, W, b, outbuf, Nn);
    } else {
        dim3 grid(Fout / 64, cdiv(Nn, 128));
        gemm_bias_tc_kernel<<<grid, 256>>>(Tbuf, W, b, outbuf, Nn, Fout, stride);
    }
}

extern "C" void kernel_launch(void* const* d_in, const int* in_sizes, int n_in,
                              void* d_out, int out_size) {
    const float* x      = (const float*)d_in[0];
    const int*   ei0    = (const int*)d_in[1];
    const int*   ei1    = (const int*)d_in[2];
    const int*   ei2    = (const int*)d_in[3];
    const float* W0     = (const float*)d_in[4];
    const float* b0     = (const float*)d_in[5];
    const float* W1     = (const float*)d_in[6];
    const float* b1     = (const float*)d_in[7];
    const float* W2     = (const float*)d_in[8];
    const float* b2     = (const float*)d_in[9];
    const int*   D0r    = (const int*)d_in[10];
    const int*   D0c    = (const int*)d_in[11];
    const float* D0v    = (const float*)d_in[12];
    const int*   D1r    = (const int*)d_in[13];
    const int*   D1c    = (const int*)d_in[14];
    const float* D1v    = (const float*)d_in[15];
    const float* linW   = (const float*)d_in[16];
    const float* linb   = (const float*)d_in[17];
    float* out = (float*)d_out;

    float *T, *h0, *P, *h1, *h2, *w, *dinv;
    cudaGetSymbolAddress((void**)&T,    g_T);
    cudaGetSymbolAddress((void**)&h0,   g_h0);
    cudaGetSymbolAddress((void**)&P,    g_P);
    cudaGetSymbolAddress((void**)&h1,   g_h1);
    cudaGetSymbolAddress((void**)&h2,   g_h2);
    cudaGetSymbolAddress((void**)&w,    g_w);
    cudaGetSymbolAddress((void**)&dinv, g_dinv);

    // Level 0: ChebConv(3 -> 128) on N0
    run_cheb(ei0, EE0, NN0, 3, 128, x, W0, b0, T, h0, dinv, w);

    // Pool 0 (fused ReLU): [N0,128] -> [N1,128]
    zero_kernel<<<cdiv(NN1 * 128, 256), 256>>>(P, NN1 * 128);
    pool_kernel<<<cdiv(100000 * 32, 256), 256>>>(D0r, D0c, D0v, h0, P, 100000, 1);

    // Level 1: ChebConv(128 -> 128) on N1
    run_cheb(ei1, EE1, NN1, 128, 128, P, W1, b1, T, h1, dinv, w);

    // Pool 1 (fused ReLU): [N1,128] -> [N2,128]
    zero_kernel<<<cdiv(NN2 * 128, 256), 256>>>(P, NN2 * 128);
    pool_kernel<<<cdiv(25000 * 32, 256), 256>>>(D1r, D1c, D1v, h1, P, 25000, 1);

    // Level 2: ChebConv(128 -> 256) on N2 (no relu)
    run_cheb(ei2, EE2, NN2, 128, 256, P, W2, b2, T, h2, dinv, w);

    // Final: Z = linW @ vec(h2) + linb
    init_out_kernel<<<1, 32>>>(linb, out);
    final_kernel<<<1024, 256>>>(linW, h2, out);
}

// round 9
// speedup vs baseline: 2.0948x; 1.2949x over previous
#include <cuda_runtime.h>
#include <cuda_bf16.h>
#include <cstdint>

// Problem constants
#define NN0 100000
#define NN1 25000
#define NN2 6250
#define EE0 600000
#define EE1 150000
#define EE2 37500
#define KCH 6

// ---------------- Scratch (device globals; no allocation allowed) ----------------
// T storage: level0 [N0,18]; level1 [N1,768]; level2 [N2,768]
__device__ __align__(16) float g_T [(size_t)NN1 * 768];
__device__ __align__(16) float g_h0[(size_t)NN0 * 128];
__device__ __align__(16) float g_h1[(size_t)NN1 * 128];
__device__ __align__(16) float g_h2[(size_t)NN2 * 256];
__device__ __align__(16) float g_wp [EE0];     // permuted edge weights (CSR order)
__device__ __align__(16) int   g_col[EE0];     // permuted source indices (CSR order)
// int scratch: degs [0,N) | degd [N,2N) | ctr [2N] | row_start [2N+1,3N+1) | cursor [3N+1,4N+1)
__device__ __align__(16) int   g_int[4 * NN0 + 2];
__device__ __align__(16) float g_dinv[NN0];

__device__ __forceinline__ uint32_t sm_u32(const void* p) {
    uint32_t r;
    asm("{.reg .u64 t; cvta.to.shared.u64 t, %1; cvt.u32.u64 %0, t;}" : "=r"(r) : "l"(p));
    return r;
}

// ---------------- CSR build kernels ----------------
// Zero EXACTLY the regions this build uses: degs[0..n), degd[0..n), *ctr.
// (Device globals are only zeroed at module load; every call/replay must re-zero,
//  and the regions are at fixed offsets independent of n.)
__global__ void zero_csr_kernel(int* __restrict__ degs, int* __restrict__ degd,
                                int* __restrict__ ctr, int n) {
    int i = blockIdx.x * blockDim.x + threadIdx.x;
    if (i < n) { degs[i] = 0; degd[i] = 0; }
    if (i == 0) *ctr = 0;
}

// histogram: degs[key1[e]]++ (optional), degd[key2[e]]++
__global__ void hist_kernel(const int* __restrict__ key1, const int* __restrict__ key2,
                            int* __restrict__ degs, int* __restrict__ degd, int E) {
    int e = blockIdx.x * blockDim.x + threadIdx.x;
    if (e >= E) return;
    if (key1) atomicAdd(&degs[key1[e]], 1);
    atomicAdd(&degd[key2[e]], 1);
}

// Allocate contiguous row slots via warp-aggregated atomic; compute dinv from src-degree.
__global__ void rowstart_kernel(const int* __restrict__ degd, const int* __restrict__ degs,
                                int* __restrict__ row_start, int* __restrict__ cursor,
                                int* __restrict__ ctr, float* __restrict__ dinv, int n) {
    int i = blockIdx.x * blockDim.x + threadIdx.x;
    int d = (i < n) ? degd[i] : 0;
    int incl = d;
#pragma unroll
    for (int off = 1; off < 32; off <<= 1) {
        int t = __shfl_up_sync(0xffffffffu, incl, off);
        if ((threadIdx.x & 31) >= off) incl += t;
    }
    int total = __shfl_sync(0xffffffffu, incl, 31);
    int base = 0;
    if ((threadIdx.x & 31) == 31 && total > 0) base = atomicAdd(ctr, total);
    base = __shfl_sync(0xffffffffu, base, 31);
    if (i < n) {
        int s = base + incl - d;
        row_start[i] = s;
        cursor[i] = s;
        if (dinv) {
            int ds = degs[i];
            dinv[i] = (ds > 0) ? rsqrtf((float)ds) : 0.0f;
        }
    }
}

// Permute edges into CSR slots. cheb: key=(src,dst), w=-(dinv[s]*dinv[d]).
// pool: srck=cols, dstk=rows, w=vals.
__global__ void scatter_kernel(const int* __restrict__ srck, const int* __restrict__ dstk,
                               const float* __restrict__ dinv, const float* __restrict__ vals,
                               int* __restrict__ cursor,
                               int* __restrict__ col, float* __restrict__ wp, int E) {
    int e = blockIdx.x * blockDim.x + threadIdx.x;
    if (e >= E) return;
    int s = srck[e], d = dstk[e];
    float wv = dinv ? -(dinv[s] * dinv[d]) : vals[e];
    int pos = atomicAdd(&cursor[d], 1);
    col[pos] = s;
    wp[pos] = wv;
}

// ---------------- Gather propagation ----------------
// F=3 (level 0), stride 18, thread per node. out = (prev? 2*acc - prev : acc)
__global__ void gather3_kernel(const int* __restrict__ rs, const int* __restrict__ degd,
                               const int* __restrict__ col, const float* __restrict__ wp,
                               const float* __restrict__ in, float* __restrict__ out,
                               const float* __restrict__ prev, int N) {
    int i = blockIdx.x * blockDim.x + threadIdx.x;
    if (i >= N) return;
    int e0 = rs[i], e1 = e0 + degd[i];
    float a0 = 0.f, a1 = 0.f, a2 = 0.f;
    for (int e = e0; e < e1; e++) {
        float c = __ldg(&wp[e]);
        const float* p = &in[(size_t)__ldg(&col[e]) * 18];
        a0 += c * p[0]; a1 += c * p[1]; a2 += c * p[2];
    }
    float* o = &out[(size_t)i * 18];
    if (prev) {
        const float* pv = &prev[(size_t)i * 18];
        o[0] = 2.f * a0 - pv[0]; o[1] = 2.f * a1 - pv[1]; o[2] = 2.f * a2 - pv[2];
    } else {
        o[0] = a0; o[1] = a1; o[2] = a2;
    }
}

// F=128, warp per node, float4 per lane. Used for props (relu=0, prev maybe) and
// pools (relu=1, prev=null, instride 128, outstride 768).
__global__ void gather128_kernel(const int* __restrict__ rs, const int* __restrict__ degd,
                                 const int* __restrict__ col, const float* __restrict__ wp,
                                 const float* __restrict__ in, int instride,
                                 float* __restrict__ out, int outstride,
                                 const float* __restrict__ prev, int prevstride,
                                 int do_relu, int N) {
    int gid = blockIdx.x * blockDim.x + threadIdx.x;
    int i = gid >> 5;
    if (i >= N) return;
    int f = (gid & 31) * 4;
    int e0 = __ldg(&rs[i]), e1 = e0 + __ldg(&degd[i]);
    float4 acc = make_float4(0.f, 0.f, 0.f, 0.f);
    for (int e = e0; e < e1; e++) {
        float c = __ldg(&wp[e]);
        int s = __ldg(&col[e]);
        float4 v = *reinterpret_cast<const float4*>(&in[(size_t)s * instride + f]);
        if (do_relu) {
            v.x = fmaxf(v.x, 0.f); v.y = fmaxf(v.y, 0.f);
            v.z = fmaxf(v.z, 0.f); v.w = fmaxf(v.w, 0.f);
        }
        acc.x += c * v.x; acc.y += c * v.y; acc.z += c * v.z; acc.w += c * v.w;
    }
    float4 o = acc;
    if (prev) {
        float4 pv = *reinterpret_cast<const float4*>(&prev[(size_t)i * prevstride + f]);
        o.x = 2.f * acc.x - pv.x; o.y = 2.f * acc.y - pv.y;
        o.z = 2.f * acc.z - pv.z; o.w = 2.f * acc.w - pv.w;
    }
    *reinterpret_cast<float4*>(&out[(size_t)i * outstride + f]) = o;
}

// out[i*os+f] = in[i*is+f]  (T0 init for level 0 only)
__global__ void copy_strided_kernel(const float* __restrict__ in, int is,
                                    float* __restrict__ out, int os, int N, int F) {
    int tid = blockIdx.x * blockDim.x + threadIdx.x;
    if (tid >= N * F) return;
    int i = tid / F, f = tid - i * F;
    out[(size_t)i * os + f] = in[(size_t)i * is + f];
}

// ---------------- Level-0 output: h0 = T[N0,18] @ W0[18,128] + b0 ----------------
__global__ void level0_out_kernel(const float* __restrict__ T, const float* __restrict__ W,
                                  const float* __restrict__ b, float* __restrict__ h0, int N) {
    int half = threadIdx.x >> 7;
    int node = blockIdx.x * 2 + half;
    int j = threadIdx.x & 127;
    __shared__ float sT[2][18];
    if (j < 18 && node < N) sT[half][j] = T[(size_t)node * 18 + j];
    __syncthreads();
    if (node >= N) return;
    float s = b[j];
#pragma unroll
    for (int t = 0; t < 18; t++) s = fmaf(sT[half][t], W[t * 128 + j], s);
    h0[(size_t)node * 128 + j] = s;
}

// ---------------- Tensor-core GEMM (bf16 3-term split, fp32 accum) ----------------
#define APAD 8
#define BPAD 8
__global__ __launch_bounds__(256) void gemm_bias_tc_kernel(
        const float* __restrict__ A, const float* __restrict__ B,
        const float* __restrict__ bias, float* __restrict__ C,
        int M, int N, int K) {
    __shared__ __nv_bfloat16 Ahi[128][32 + APAD];
    __shared__ __nv_bfloat16 Alo[128][32 + APAD];
    __shared__ __nv_bfloat16 Bhi[32][64 + BPAD];
    __shared__ __nv_bfloat16 Blo[32][64 + BPAD];

    const int tid = threadIdx.x;
    const int lane = tid & 31;
    const int warp = tid >> 5;
    const int wm = warp & 3;
    const int wn = warp >> 2;
    const int row0 = blockIdx.y * 128;
    const int col0 = blockIdx.x * 64;

    float acc[2][4][4];
#pragma unroll
    for (int i = 0; i < 2; i++)
#pragma unroll
        for (int j = 0; j < 4; j++)
#pragma unroll
            for (int v = 0; v < 4; v++) acc[i][j][v] = 0.0f;

    for (int k0 = 0; k0 < K; k0 += 32) {
#pragma unroll
        for (int l = 0; l < 4; l++) {
            int idx = tid + l * 256;
            int r = idx >> 3;
            int kk = (idx & 7) * 4;
            float4 av = make_float4(0, 0, 0, 0);
            int gr = row0 + r;
            if (gr < M) av = *reinterpret_cast<const float4*>(&A[(size_t)gr * K + k0 + kk]);
            __nv_bfloat16 h0 = __float2bfloat16_rn(av.x);
            __nv_bfloat16 h1 = __float2bfloat16_rn(av.y);
            __nv_bfloat16 h2 = __float2bfloat16_rn(av.z);
            __nv_bfloat16 h3 = __float2bfloat16_rn(av.w);
            Ahi[r][kk + 0] = h0; Ahi[r][kk + 1] = h1; Ahi[r][kk + 2] = h2; Ahi[r][kk + 3] = h3;
            Alo[r][kk + 0] = __float2bfloat16_rn(av.x - __bfloat162float(h0));
            Alo[r][kk + 1] = __float2bfloat16_rn(av.y - __bfloat162float(h1));
            Alo[r][kk + 2] = __float2bfloat16_rn(av.z - __bfloat162float(h2));
            Alo[r][kk + 3] = __float2bfloat16_rn(av.w - __bfloat162float(h3));
        }
#pragma unroll
        for (int l = 0; l < 2; l++) {
            int idx = tid + l * 256;
            int r = idx >> 4;
            int nn = (idx & 15) * 4;
            float4 bv = *reinterpret_cast<const float4*>(&B[(size_t)(k0 + r) * N + col0 + nn]);
            __nv_bfloat16 h0 = __float2bfloat16_rn(bv.x);
            __nv_bfloat16 h1 = __float2bfloat16_rn(bv.y);
            __nv_bfloat16 h2 = __float2bfloat16_rn(bv.z);
            __nv_bfloat16 h3 = __float2bfloat16_rn(bv.w);
            Bhi[r][nn + 0] = h0; Bhi[r][nn + 1] = h1; Bhi[r][nn + 2] = h2; Bhi[r][nn + 3] = h3;
            Blo[r][nn + 0] = __float2bfloat16_rn(bv.x - __bfloat162float(h0));
            Blo[r][nn + 1] = __float2bfloat16_rn(bv.y - __bfloat162float(h1));
            Blo[r][nn + 2] = __float2bfloat16_rn(bv.z - __bfloat162float(h2));
            Blo[r][nn + 3] = __float2bfloat16_rn(bv.w - __bfloat162float(h3));
        }
        __syncthreads();

#pragma unroll
        for (int ks = 0; ks < 32; ks += 16) {
            uint32_t ah[2][4], al[2][4];
#pragma unroll
            for (int mf = 0; mf < 2; mf++) {
                int ar = wm * 32 + mf * 16 + (lane & 15);
                int ac = ks + (lane >> 4) * 8;
                uint32_t addr_h = sm_u32(&Ahi[ar][ac]);
                asm volatile("ldmatrix.sync.aligned.m8n8.x4.shared.b16 {%0,%1,%2,%3}, [%4];"
                             : "=r"(ah[mf][0]), "=r"(ah[mf][1]), "=r"(ah[mf][2]), "=r"(ah[mf][3])
                             : "r"(addr_h));
                uint32_t addr_l = sm_u32(&Alo[ar][ac]);
                asm volatile("ldmatrix.sync.aligned.m8n8.x4.shared.b16 {%0,%1,%2,%3}, [%4];"
                             : "=r"(al[mf][0]), "=r"(al[mf][1]), "=r"(al[mf][2]), "=r"(al[mf][3])
                             : "r"(addr_l));
            }
#pragma unroll
            for (int p = 0; p < 2; p++) {
                int bk = ks + (lane & 15);
                int bn = wn * 32 + p * 16 + (lane >> 4) * 8;
                uint32_t bh[4], bl[4];
                uint32_t addr_h = sm_u32(&Bhi[bk][bn]);
                asm volatile("ldmatrix.sync.aligned.m8n8.x4.trans.shared.b16 {%0,%1,%2,%3}, [%4];"
                             : "=r"(bh[0]), "=r"(bh[1]), "=r"(bh[2]), "=r"(bh[3])
                             : "r"(addr_h));
                uint32_t addr_l = sm_u32(&Blo[bk][bn]);
                asm volatile("ldmatrix.sync.aligned.m8n8.x4.trans.shared.b16 {%0,%1,%2,%3}, [%4];"
                             : "=r"(bl[0]), "=r"(bl[1]), "=r"(bl[2]), "=r"(bl[3])
                             : "r"(addr_l));
#pragma unroll
                for (int mf = 0; mf < 2; mf++) {
#pragma unroll
                    for (int q = 0; q < 2; q++) {
                        int nf = p * 2 + q;
                        float* c = acc[mf][nf];
                        asm volatile(
                            "mma.sync.aligned.m16n8k16.row.col.f32.bf16.bf16.f32 "
                            "{%0,%1,%2,%3}, {%4,%5,%6,%7}, {%8,%9}, {%0,%1,%2,%3};"
                            : "+f"(c[0]), "+f"(c[1]), "+f"(c[2]), "+f"(c[3])
                            : "r"(ah[mf][0]), "r"(ah[mf][1]), "r"(ah[mf][2]), "r"(ah[mf][3]),
                              "r"(bh[2 * q]), "r"(bh[2 * q + 1]));
                        asm volatile(
                            "mma.sync.aligned.m16n8k16.row.col.f32.bf16.bf16.f32 "
                            "{%0,%1,%2,%3}, {%4,%5,%6,%7}, {%8,%9}, {%0,%1,%2,%3};"
                            : "+f"(c[0]), "+f"(c[1]), "+f"(c[2]), "+f"(c[3])
                            : "r"(ah[mf][0]), "r"(ah[mf][1]), "r"(ah[mf][2]), "r"(ah[mf][3]),
                              "r"(bl[2 * q]), "r"(bl[2 * q + 1]));
                        asm volatile(
                            "mma.sync.aligned.m16n8k16.row.col.f32.bf16.bf16.f32 "
                            "{%0,%1,%2,%3}, {%4,%5,%6,%7}, {%8,%9}, {%0,%1,%2,%3};"
                            : "+f"(c[0]), "+f"(c[1]), "+f"(c[2]), "+f"(c[3])
                            : "r"(al[mf][0]), "r"(al[mf][1]), "r"(al[mf][2]), "r"(al[mf][3]),
                              "r"(bh[2 * q]), "r"(bh[2 * q + 1]));
                    }
                }
            }
        }
        __syncthreads();
    }

#pragma unroll
    for (int mf = 0; mf < 2; mf++) {
#pragma unroll
        for (int nf = 0; nf < 4; nf++) {
            int col = col0 + wn * 32 + nf * 8 + (lane & 3) * 2;
            float bx = bias[col], by = bias[col + 1];
            int r0 = row0 + wm * 32 + mf * 16 + (lane >> 2);
            if (r0 < M) {
                float2 o = make_float2(acc[mf][nf][0] + bx, acc[mf][nf][1] + by);
                *reinterpret_cast<float2*>(&C[(size_t)r0 * N + col]) = o;
            }
            int r1 = r0 + 8;
            if (r1 < M) {
                float2 o = make_float2(acc[mf][nf][2] + bx, acc[mf][nf][3] + by);
                *reinterpret_cast<float2*>(&C[(size_t)r1 * N + col]) = o;
            }
        }
    }
}

// ---------------- Final: Z = linW[10, 1600000] @ h2 + linb ----------------
__global__ void init_out_kernel(const float* __restrict__ linb, float* __restrict__ out) {
    int i = threadIdx.x;
    if (i < 10) out[i] = linb[i];
}

__global__ void final_kernel(const float* __restrict__ linW, const float* __restrict__ h,
                             float* __restrict__ out) {
    const int VL4 = (NN2 * 256) / 4;
    float acc[10];
#pragma unroll
    for (int j = 0; j < 10; j++) acc[j] = 0.0f;
    const float4* h4 = reinterpret_cast<const float4*>(h);
    for (int i = blockIdx.x * blockDim.x + threadIdx.x; i < VL4; i += gridDim.x * blockDim.x) {
        float4 hv = h4[i];
#pragma unroll
        for (int j = 0; j < 10; j++) {
            float4 wv = reinterpret_cast<const float4*>(linW + (size_t)j * (NN2 * 256))[i];
            acc[j] += wv.x * hv.x + wv.y * hv.y + wv.z * hv.z + wv.w * hv.w;
        }
    }
    __shared__ float red[256];
#pragma unroll
    for (int j = 0; j < 10; j++) {
        red[threadIdx.x] = acc[j];
        __syncthreads();
        for (int s = 128; s > 0; s >>= 1) {
            if (threadIdx.x < (unsigned)s) red[threadIdx.x] += red[threadIdx.x + s];
            __syncthreads();
        }
        if (threadIdx.x == 0) atomicAdd(&out[j], red[0]);
        __syncthreads();
    }
}

// ---------------- Host-side driver ----------------
static inline int cdiv(int a, int b) { return (a + b - 1) / b; }

struct CsrBufs {
    int* degs; int* degd; int* ctr; int* rs; int* cur;
    int* col; float* wp; float* dinv;
};

// Build CSR keyed by dstk. cheb=true: weights from dinv (computed from srck degree).
// cheb=false: weights from vals.
static void build_csr(const int* srck, const int* dstk, const float* vals,
                      int E, int Nn, const CsrBufs& B, bool cheb) {
    // Zero exactly degs[0..Nn), degd[0..Nn), ctr — regions are at FIXED offsets,
    // so the zeroing must target them explicitly (stale counts otherwise persist
    // across builds/replays; this was the R6 divergence bug).
    zero_csr_kernel<<<cdiv(Nn, 256), 256>>>(B.degs, B.degd, B.ctr, Nn);
    if (cheb) {
        hist_kernel<<<cdiv(E, 256), 256>>>(srck, dstk, B.degs, B.degd, E);
        rowstart_kernel<<<cdiv(Nn, 256), 256>>>(B.degd, B.degs, B.rs, B.cur, B.ctr, B.dinv, Nn);
        scatter_kernel<<<cdiv(E, 256), 256>>>(srck, dstk, B.dinv, nullptr, B.cur, B.col, B.wp, E);
    } else {
        hist_kernel<<<cdiv(E, 256), 256>>>(nullptr, dstk, nullptr, B.degd, E);
        rowstart_kernel<<<cdiv(Nn, 256), 256>>>(B.degd, nullptr, B.rs, B.cur, B.ctr, nullptr, Nn);
        scatter_kernel<<<cdiv(E, 256), 256>>>(srck, dstk, nullptr, vals, B.cur, B.col, B.wp, E);
    }
}

// ChebConv level with F=128 inputs. Assumes T0 (slot 0 of Tbuf, stride 768) already populated.
static void run_cheb128(const int* ei, int E, int Nn, int Fout,
                        const float* W, const float* b,
                        float* Tbuf, float* outbuf, const CsrBufs& B) {
    build_csr(ei, ei + E, nullptr, E, Nn, B, true);
    const int st = 768;
    int thr = Nn * 32;
    // T1 = prop(T0)
    gather128_kernel<<<cdiv(thr, 256), 256>>>(B.rs, B.degd, B.col, B.wp,
                                              Tbuf, st, Tbuf + 128, st, nullptr, st, 0, Nn);
    for (int k = 2; k < KCH; k++) {
        gather128_kernel<<<cdiv(thr, 256), 256>>>(B.rs, B.degd, B.col, B.wp,
                                                  Tbuf + (size_t)(k - 1) * 128, st,
                                                  Tbuf + (size_t)k * 128, st,
                                                  Tbuf + (size_t)(k - 2) * 128, st, 0, Nn);
    }
    dim3 grid(Fout / 64, cdiv(Nn, 128));
    gemm_bias_tc_kernel<<<grid, 256>>>(Tbuf, W, b, outbuf, Nn, Fout, st);
}

extern "C" void kernel_launch(void* const* d_in, const int* in_sizes, int n_in,
                              void* d_out, int out_size) {
    const float* x      = (const float*)d_in[0];
    const int*   ei0    = (const int*)d_in[1];
    const int*   ei1    = (const int*)d_in[2];
    const int*   ei2    = (const int*)d_in[3];
    const float* W0     = (const float*)d_in[4];
    const float* b0     = (const float*)d_in[5];
    const float* W1     = (const float*)d_in[6];
    const float* b1     = (const float*)d_in[7];
    const float* W2     = (const float*)d_in[8];
    const float* b2     = (const float*)d_in[9];
    const int*   D0r    = (const int*)d_in[10];
    const int*   D0c    = (const int*)d_in[11];
    const float* D0v    = (const float*)d_in[12];
    const int*   D1r    = (const int*)d_in[13];
    const int*   D1c    = (const int*)d_in[14];
    const float* D1v    = (const float*)d_in[15];
    const float* linW   = (const float*)d_in[16];
    const float* linb   = (const float*)d_in[17];
    float* out = (float*)d_out;

    float *T, *h0, *h1, *h2, *wp, *dinv;
    int *ib, *col;
    cudaGetSymbolAddress((void**)&T,    g_T);
    cudaGetSymbolAddress((void**)&h0,   g_h0);
    cudaGetSymbolAddress((void**)&h1,   g_h1);
    cudaGetSymbolAddress((void**)&h2,   g_h2);
    cudaGetSymbolAddress((void**)&wp,   g_wp);
    cudaGetSymbolAddress((void**)&col,  g_col);
    cudaGetSymbolAddress((void**)&ib,   g_int);
    cudaGetSymbolAddress((void**)&dinv, g_dinv);

    CsrBufs B;
    B.degs = ib;
    B.degd = ib + NN0;
    B.ctr  = ib + 2 * NN0;
    B.rs   = ib + 2 * NN0 + 1;
    B.cur  = ib + 3 * NN0 + 1;
    B.col  = col;
    B.wp   = wp;
    B.dinv = dinv;

    // ---- Level 0: ChebConv(3 -> 128) on N0 ----
    build_csr(ei0, ei0 + EE0, nullptr, EE0, NN0, B, true);
    // T0 = x  (stride 3 -> 18)
    copy_strided_kernel<<<cdiv(NN0 * 3, 256), 256>>>(x, 3, T, 18, NN0, 3);
    // T1 = prop(T0)
    gather3_kernel<<<cdiv(NN0, 256), 256>>>(B.rs, B.degd, B.col, B.wp, T, T + 3, nullptr, NN0);
    for (int k = 2; k < KCH; k++) {
        gather3_kernel<<<cdiv(NN0, 256), 256>>>(B.rs, B.degd, B.col, B.wp,
                                                T + (k - 1) * 3, T + k * 3, T + (k - 2) * 3, NN0);
    }
    level0_out_kernel<<<cdiv(NN0, 2), 256>>>(T, W0, b0, h0, NN0);

    // ---- Pool 0 (fused ReLU): h0 [N0,128] -> T0 slot of level-1 T [N1,768] ----
    build_csr(D0c, D0r, D0v, 100000, NN1, B, false);
    gather128_kernel<<<cdiv(NN1 * 32, 256), 256>>>(B.rs, B.degd, B.col, B.wp,
                                                   h0, 128, T, 768, nullptr, 768, 1, NN1);

    // ---- Level 1: ChebConv(128 -> 128) on N1 ----
    run_cheb128(ei1, EE1, NN1, 128, W1, b1, T, h1, B);

    // ---- Pool 1 (fused ReLU): h1 [N1,128] -> T0 slot of level-2 T [N2,768] ----
    build_csr(D1c, D1r, D1v, 25000, NN2, B, false);
    gather128_kernel<<<cdiv(NN2 * 32, 256), 256>>>(B.rs, B.degd, B.col, B.wp,
                                                   h1, 128, T, 768, nullptr, 768, 1, NN2);

    // ---- Level 2: ChebConv(128 -> 256) on N2 (no relu) ----
    run_cheb128(ei2, EE2, NN2, 256, W2, b2, T, h2, B);

    // ---- Final: Z = linW @ vec(h2) + linb ----
    init_out_kernel<<<1, 32>>>(linb, out);
    final_kernel<<<1024, 256>>>(linW, h2, out);
}

// round 14
// speedup vs baseline: 2.3227x; 1.1088x over previous
#include <cuda_runtime.h>
#include <cuda_bf16.h>
#include <cstdint>

// Problem constants
#define NN0 100000
#define NN1 25000
#define NN2 6250
#define EE0 600000
#define EE1 150000
#define EE2 37500
#define KCH 6

#define E_P0 100000
#define E_P1 25000
#define E_TOT (EE0 + EE1 + EE2 + E_P0 + E_P1)          // 912500
#define N_TOT (NN0 + NN1 + NN2 + NN1 + NN2)            // 162500

// Node-arena bases per graph (C0, C1, C2, P0, P1)
#define NB_C0 0
#define NB_C1 (NN0)
#define NB_C2 (NN0 + NN1)
#define NB_P0 (NN0 + NN1 + NN2)
#define NB_P1 (NN0 + NN1 + NN2 + NN1)

// ---------------- Scratch (device globals; no allocation allowed) ----------------
// T storage: level0 [N0,24] (6 slots x float4); level1 [N1,768]; level2 [N2,768]
__device__ __align__(16) float g_T [(size_t)NN1 * 768];
__device__ __align__(16) float g_h0[(size_t)NN0 * 128];
__device__ __align__(16) float g_h1[(size_t)NN1 * 128];
__device__ __align__(16) float g_h2[(size_t)NN2 * 256];
__device__ __align__(16) float g_wp [E_TOT];   // permuted edge weights (CSR order), one arena
__device__ __align__(16) int   g_col[E_TOT];   // permuted LOCAL source indices, one arena
// int arena: degs[N_TOT] | degd[N_TOT] | rs[N_TOT] | cur[N_TOT] | ctr
__device__ __align__(16) int   g_int[4 * N_TOT + 4];
__device__ __align__(16) float g_dinv[N_TOT];

struct GDesc {
    const int* src;
    const int* dst;
    const float* vals;   // pool weights (null for cheb)
    int ebase;           // edge base in concatenated edge space
    int E;
    int nbase;           // node base in node arena
    int cheb;            // 1 = cheb normalization, 0 = pool vals
};

__device__ __forceinline__ uint32_t sm_u32(const void* p) {
    uint32_t r;
    asm("{.reg .u64 t; cvta.to.shared.u64 t, %1; cvt.u32.u64 %0, t;}" : "=r"(r) : "l"(p));
    return r;
}

// ---------------- Batched CSR build (4 launches for all 5 graphs) ----------------
// Zero degs[0,NT), degd[NT,2NT), ctr (at 4NT). Packed: indices [0,2NT) + one.
__global__ void zero_build_kernel(int* __restrict__ ib) {
    int i = blockIdx.x * blockDim.x + threadIdx.x;
    if (i < 2 * N_TOT) ib[i] = 0;
    if (i == 0) ib[4 * N_TOT] = 0;
}

__global__ void hist_all_kernel(GDesc g0, GDesc g1, GDesc g2, GDesc g3, GDesc g4,
                                int* __restrict__ degs, int* __restrict__ degd) {
    int gid = blockIdx.x * blockDim.x + threadIdx.x;
    if (gid >= E_TOT) return;
    GDesc g = g0;
    if (gid >= g4.ebase) g = g4;
    else if (gid >= g3.ebase) g = g3;
    else if (gid >= g2.ebase) g = g2;
    else if (gid >= g1.ebase) g = g1;
    int e = gid - g.ebase;
    int d = g.dst[e];
    atomicAdd(&degd[g.nbase + d], 1);
    if (g.cheb) atomicAdd(&degs[g.nbase + g.src[e]], 1);
}

// Single GLOBAL slot counter: rows of different graphs interleave freely in the
// col/wp arena — per-row contiguity is all the gather needs.
__global__ void rowstart_all_kernel(const int* __restrict__ degd, const int* __restrict__ degs,
                                    int* __restrict__ rs, int* __restrict__ cur,
                                    int* __restrict__ ctr, float* __restrict__ dinv) {
    int i = blockIdx.x * blockDim.x + threadIdx.x;
    int d = (i < N_TOT) ? degd[i] : 0;
    int incl = d;
#pragma unroll
    for (int off = 1; off < 32; off <<= 1) {
        int t = __shfl_up_sync(0xffffffffu, incl, off);
        if ((threadIdx.x & 31) >= off) incl += t;
    }
    int total = __shfl_sync(0xffffffffu, incl, 31);
    int base = 0;
    if ((threadIdx.x & 31) == 31 && total > 0) base = atomicAdd(ctr, total);
    base = __shfl_sync(0xffffffffu, base, 31);
    if (i < N_TOT) {
        int s = base + incl - d;
        rs[i] = s;
        cur[i] = s;
        int ds = degs[i];
        dinv[i] = (ds > 0) ? rsqrtf((float)ds) : 0.0f;
    }
}

__global__ void scatter_all_kernel(GDesc g0, GDesc g1, GDesc g2, GDesc g3, GDesc g4,
                                   const float* __restrict__ dinv, int* __restrict__ cur,
                                   int* __restrict__ col, float* __restrict__ wp) {
    int gid = blockIdx.x * blockDim.x + threadIdx.x;
    if (gid >= E_TOT) return;
    GDesc g = g0;
    if (gid >= g4.ebase) g = g4;
    else if (gid >= g3.ebase) g = g3;
    else if (gid >= g2.ebase) g = g2;
    else if (gid >= g1.ebase) g = g1;
    int e = gid - g.ebase;
    int s = g.src[e], d = g.dst[e];
    float w = g.cheb ? -(dinv[g.nbase + s] * dinv[g.nbase + d]) : g.vals[e];
    int pos = atomicAdd(&cur[g.nbase + d], 1);
    col[pos] = s;
    wp[pos] = w;
}

// ---------------- Gather propagation ----------------
// Level 0: T layout [N0][24], slot k at float offset 4k (float4-aligned).
// One LDG.128 per edge. out = (prev ? 2*acc - prev : acc)
__global__ void gather3_kernel(const int* __restrict__ rs, const int* __restrict__ degd,
                               const int* __restrict__ col, const float* __restrict__ wp,
                               const float* __restrict__ in, float* __restrict__ out,
                               const float* __restrict__ prev, int N) {
    int i = blockIdx.x * blockDim.x + threadIdx.x;
    if (i >= N) return;
    int e0 = rs[i], e1 = e0 + degd[i];
    float4 a = make_float4(0.f, 0.f, 0.f, 0.f);
    for (int e = e0; e < e1; e++) {
        float c = __ldg(&wp[e]);
        float4 v = *reinterpret_cast<const float4*>(&in[(size_t)__ldg(&col[e]) * 24]);
        a.x += c * v.x; a.y += c * v.y; a.z += c * v.z;
    }
    float4 o = a;
    if (prev) {
        float4 pv = *reinterpret_cast<const float4*>(&prev[(size_t)i * 24]);
        o.x = 2.f * a.x - pv.x; o.y = 2.f * a.y - pv.y; o.z = 2.f * a.z - pv.z;
    }
    o.w = 0.f;
    *reinterpret_cast<float4*>(&out[(size_t)i * 24]) = o;
}

// F=128, warp per node, float4 per lane.
__global__ void gather128_kernel(const int* __restrict__ rs, const int* __restrict__ degd,
                                 const int* __restrict__ col, const float* __restrict__ wp,
                                 const float* __restrict__ in, int instride,
                                 float* __restrict__ out, int outstride,
                                 const float* __restrict__ prev, int prevstride,
                                 int do_relu, int N) {
    int gid = blockIdx.x * blockDim.x + threadIdx.x;
    int i = gid >> 5;
    if (i >= N) return;
    int f = (gid & 31) * 4;
    int e0 = __ldg(&rs[i]), e1 = e0 + __ldg(&degd[i]);
    float4 acc = make_float4(0.f, 0.f, 0.f, 0.f);
    for (int e = e0; e < e1; e++) {
        float c = __ldg(&wp[e]);
        int s = __ldg(&col[e]);
        float4 v = *reinterpret_cast<const float4*>(&in[(size_t)s * instride + f]);
        if (do_relu) {
            v.x = fmaxf(v.x, 0.f); v.y = fmaxf(v.y, 0.f);
            v.z = fmaxf(v.z, 0.f); v.w = fmaxf(v.w, 0.f);
        }
        acc.x += c * v.x; acc.y += c * v.y; acc.z += c * v.z; acc.w += c * v.w;
    }
    float4 o = acc;
    if (prev) {
        float4 pv = *reinterpret_cast<const float4*>(&prev[(size_t)i * prevstride + f]);
        o.x = 2.f * acc.x - pv.x; o.y = 2.f * acc.y - pv.y;
        o.z = 2.f * acc.z - pv.z; o.w = 2.f * acc.w - pv.w;
    }
    *reinterpret_cast<float4*>(&out[(size_t)i * outstride + f]) = o;
}

// T0 init for level 0: x [N,3] -> T [N][24] slot 0 as float4 {x,y,z,0}
__global__ void copy4_kernel(const float* __restrict__ x, float* __restrict__ T, int N) {
    int i = blockIdx.x * blockDim.x + threadIdx.x;
    if (i >= N) return;
    float a = x[3 * i], b = x[3 * i + 1], c = x[3 * i + 2];
    *reinterpret_cast<float4*>(&T[(size_t)i * 24]) = make_float4(a, b, c, 0.f);
}

// ---------------- Level-0 output: h0 = T[N0,(6x3 in 24)] @ W0[18,128] + b0 ----------------
__global__ void level0_out_kernel(const float* __restrict__ T, const float* __restrict__ W,
                                  const float* __restrict__ b, float* __restrict__ h0, int N) {
    int half = threadIdx.x >> 7;
    int node = blockIdx.x * 2 + half;
    int j = threadIdx.x & 127;
    __shared__ float sT[2][24];
    if (j < 24 && node < N) sT[half][j] = T[(size_t)node * 24 + j];
    __syncthreads();
    if (node >= N) return;
    float s = b[j];
#pragma unroll
    for (int t = 0; t < 18; t++)
        s = fmaf(sT[half][(t / 3) * 4 + (t % 3)], W[t * 128 + j], s);
    h0[(size_t)node * 128 + j] = s;
}

// ---------------- Tensor-core GEMM (bf16 3-term split, fp32 accum) ----------------
#define APAD 8
#define BPAD 8
__global__ __launch_bounds__(256) void gemm_bias_tc_kernel(
        const float* __restrict__ A, const float* __restrict__ B,
        const float* __restrict__ bias, float* __restrict__ C,
        int M, int N, int K) {
    __shared__ __nv_bfloat16 Ahi[128][32 + APAD];
    __shared__ __nv_bfloat16 Alo[128][32 + APAD];
    __shared__ __nv_bfloat16 Bhi[32][64 + BPAD];
    __shared__ __nv_bfloat16 Blo[32][64 + BPAD];

    const int tid = threadIdx.x;
    const int lane = tid & 31;
    const int warp = tid >> 5;
    const int wm = warp & 3;
    const int wn = warp >> 2;
    const int row0 = blockIdx.y * 128;
    const int col0 = blockIdx.x * 64;

    float acc[2][4][4];
#pragma unroll
    for (int i = 0; i < 2; i++)
#pragma unroll
        for (int j = 0; j < 4; j++)
#pragma unroll
            for (int v = 0; v < 4; v++) acc[i][j][v] = 0.0f;

    for (int k0 = 0; k0 < K; k0 += 32) {
#pragma unroll
        for (int l = 0; l < 4; l++) {
            int idx = tid + l * 256;
            int r = idx >> 3;
            int kk = (idx & 7) * 4;
            float4 av = make_float4(0, 0, 0, 0);
            int gr = row0 + r;
            if (gr < M) av = *reinterpret_cast<const float4*>(&A[(size_t)gr * K + k0 + kk]);
            __nv_bfloat16 h0 = __float2bfloat16_rn(av.x);
            __nv_bfloat16 h1 = __float2bfloat16_rn(av.y);
            __nv_bfloat16 h2 = __float2bfloat16_rn(av.z);
            __nv_bfloat16 h3 = __float2bfloat16_rn(av.w);
            Ahi[r][kk + 0] = h0; Ahi[r][kk + 1] = h1; Ahi[r][kk + 2] = h2; Ahi[r][kk + 3] = h3;
            Alo[r][kk + 0] = __float2bfloat16_rn(av.x - __bfloat162float(h0));
            Alo[r][kk + 1] = __float2bfloat16_rn(av.y - __bfloat162float(h1));
            Alo[r][kk + 2] = __float2bfloat16_rn(av.z - __bfloat162float(h2));
            Alo[r][kk + 3] = __float2bfloat16_rn(av.w - __bfloat162float(h3));
        }
#pragma unroll
        for (int l = 0; l < 2; l++) {
            int idx = tid + l * 256;
            int r = idx >> 4;
            int nn = (idx & 15) * 4;
            float4 bv = *reinterpret_cast<const float4*>(&B[(size_t)(k0 + r) * N + col0 + nn]);
            __nv_bfloat16 h0 = __float2bfloat16_rn(bv.x);
            __nv_bfloat16 h1 = __float2bfloat16_rn(bv.y);
            __nv_bfloat16 h2 = __float2bfloat16_rn(bv.z);
            __nv_bfloat16 h3 = __float2bfloat16_rn(bv.w);
            Bhi[r][nn + 0] = h0; Bhi[r][nn + 1] = h1; Bhi[r][nn + 2] = h2; Bhi[r][nn + 3] = h3;
            Blo[r][nn + 0] = __float2bfloat16_rn(bv.x - __bfloat162float(h0));
            Blo[r][nn + 1] = __float2bfloat16_rn(bv.y - __bfloat162float(h1));
            Blo[r][nn + 2] = __float2bfloat16_rn(bv.z - __bfloat162float(h2));
            Blo[r][nn + 3] = __float2bfloat16_rn(bv.w - __bfloat162float(h3));
        }
        __syncthreads();

#pragma unroll
        for (int ks = 0; ks < 32; ks += 16) {
            uint32_t ah[2][4], al[2][4];
#pragma unroll
            for (int mf = 0; mf < 2; mf++) {
                int ar = wm * 32 + mf * 16 + (lane & 15);
                int ac = ks + (lane >> 4) * 8;
                uint32_t addr_h = sm_u32(&Ahi[ar][ac]);
                asm volatile("ldmatrix.sync.aligned.m8n8.x4.shared.b16 {%0,%1,%2,%3}, [%4];"
                             : "=r"(ah[mf][0]), "=r"(ah[mf][1]), "=r"(ah[mf][2]), "=r"(ah[mf][3])
                             : "r"(addr_h));
                uint32_t addr_l = sm_u32(&Alo[ar][ac]);
                asm volatile("ldmatrix.sync.aligned.m8n8.x4.shared.b16 {%0,%1,%2,%3}, [%4];"
                             : "=r"(al[mf][0]), "=r"(al[mf][1]), "=r"(al[mf][2]), "=r"(al[mf][3])
                             : "r"(addr_l));
            }
#pragma unroll
            for (int p = 0; p < 2; p++) {
                int bk = ks + (lane & 15);
                int bn = wn * 32 + p * 16 + (lane >> 4) * 8;
                uint32_t bh[4], bl[4];
                uint32_t addr_h = sm_u32(&Bhi[bk][bn]);
                asm volatile("ldmatrix.sync.aligned.m8n8.x4.trans.shared.b16 {%0,%1,%2,%3}, [%4];"
                             : "=r"(bh[0]), "=r"(bh[1]), "=r"(bh[2]), "=r"(bh[3])
                             : "r"(addr_h));
                uint32_t addr_l = sm_u32(&Blo[bk][bn]);
                asm volatile("ldmatrix.sync.aligned.m8n8.x4.trans.shared.b16 {%0,%1,%2,%3}, [%4];"
                             : "=r"(bl[0]), "=r"(bl[1]), "=r"(bl[2]), "=r"(bl[3])
                             : "r"(addr_l));
#pragma unroll
                for (int mf = 0; mf < 2; mf++) {
#pragma unroll
                    for (int q = 0; q < 2; q++) {
                        int nf = p * 2 + q;
                        float* c = acc[mf][nf];
                        asm volatile(
                            "mma.sync.aligned.m16n8k16.row.col.f32.bf16.bf16.f32 "
                            "{%0,%1,%2,%3}, {%4,%5,%6,%7}, {%8,%9}, {%0,%1,%2,%3};"
                            : "+f"(c[0]), "+f"(c[1]), "+f"(c[2]), "+f"(c[3])
                            : "r"(ah[mf][0]), "r"(ah[mf][1]), "r"(ah[mf][2]), "r"(ah[mf][3]),
                              "r"(bh[2 * q]), "r"(bh[2 * q + 1]));
                        asm volatile(
                            "mma.sync.aligned.m16n8k16.row.col.f32.bf16.bf16.f32 "
                            "{%0,%1,%2,%3}, {%4,%5,%6,%7}, {%8,%9}, {%0,%1,%2,%3};"
                            : "+f"(c[0]), "+f"(c[1]), "+f"(c[2]), "+f"(c[3])
                            : "r"(ah[mf][0]), "r"(ah[mf][1]), "r"(ah[mf][2]), "r"(ah[mf][3]),
                              "r"(bl[2 * q]), "r"(bl[2 * q + 1]));
                        asm volatile(
                            "mma.sync.aligned.m16n8k16.row.col.f32.bf16.bf16.f32 "
                            "{%0,%1,%2,%3}, {%4,%5,%6,%7}, {%8,%9}, {%0,%1,%2,%3};"
                            : "+f"(c[0]), "+f"(c[1]), "+f"(c[2]), "+f"(c[3])
                            : "r"(al[mf][0]), "r"(al[mf][1]), "r"(al[mf][2]), "r"(al[mf][3]),
                              "r"(bh[2 * q]), "r"(bh[2 * q + 1]));
                    }
                }
            }
        }
        __syncthreads();
    }

#pragma unroll
    for (int mf = 0; mf < 2; mf++) {
#pragma unroll
        for (int nf = 0; nf < 4; nf++) {
            int col = col0 + wn * 32 + nf * 8 + (lane & 3) * 2;
            float bx = bias[col], by = bias[col + 1];
            int r0 = row0 + wm * 32 + mf * 16 + (lane >> 2);
            if (r0 < M) {
                float2 o = make_float2(acc[mf][nf][0] + bx, acc[mf][nf][1] + by);
                *reinterpret_cast<float2*>(&C[(size_t)r0 * N + col]) = o;
            }
            int r1 = r0 + 8;
            if (r1 < M) {
                float2 o = make_float2(acc[mf][nf][2] + bx, acc[mf][nf][3] + by);
                *reinterpret_cast<float2*>(&C[(size_t)r1 * N + col]) = o;
            }
        }
    }
}

// ---------------- Final: Z = linW[10, 1600000] @ h2 + linb ----------------
__global__ void init_out_kernel(const float* __restrict__ linb, float* __restrict__ out) {
    int i = threadIdx.x;
    if (i < 10) out[i] = linb[i];
}

__global__ void final_kernel(const float* __restrict__ linW, const float* __restrict__ h,
                             float* __restrict__ out) {
    const int VL4 = (NN2 * 256) / 4;
    float acc[10];
#pragma unroll
    for (int j = 0; j < 10; j++) acc[j] = 0.0f;
    const float4* h4 = reinterpret_cast<const float4*>(h);
    for (int i = blockIdx.x * blockDim.x + threadIdx.x; i < VL4; i += gridDim.x * blockDim.x) {
        float4 hv = h4[i];
#pragma unroll
        for (int j = 0; j < 10; j++) {
            float4 wv = reinterpret_cast<const float4*>(linW + (size_t)j * (NN2 * 256))[i];
            acc[j] += wv.x * hv.x + wv.y * hv.y + wv.z * hv.z + wv.w * hv.w;
        }
    }
    __shared__ float red[256];
#pragma unroll
    for (int j = 0; j < 10; j++) {
        red[threadIdx.x] = acc[j];
        __syncthreads();
        for (int s = 128; s > 0; s >>= 1) {
            if (threadIdx.x < (unsigned)s) red[threadIdx.x] += red[threadIdx.x + s];
            __syncthreads();
        }
        if (threadIdx.x == 0) atomicAdd(&out[j], red[0]);
        __syncthreads();
    }
}

// ---------------- Host-side driver ----------------
static inline int cdiv(int a, int b) { return (a + b - 1) / b; }

extern "C" void kernel_launch(void* const* d_in, const int* in_sizes, int n_in,
                              void* d_out, int out_size) {
    const float* x      = (const float*)d_in[0];
    const int*   ei0    = (const int*)d_in[1];
    const int*   ei1    = (const int*)d_in[2];
    const int*   ei2    = (const int*)d_in[3];
    const float* W0     = (const float*)d_in[4];
    const float* b0     = (const float*)d_in[5];
    const float* W1     = (const float*)d_in[6];
    const float* b1     = (const float*)d_in[7];
    const float* W2     = (const float*)d_in[8];
    const float* b2     = (const float*)d_in[9];
    const int*   D0r    = (const int*)d_in[10];
    const int*   D0c    = (const int*)d_in[11];
    const float* D0v    = (const float*)d_in[12];
    const int*   D1r    = (const int*)d_in[13];
    const int*   D1c    = (const int*)d_in[14];
    const float* D1v    = (const float*)d_in[15];
    const float* linW   = (const float*)d_in[16];
    const float* linb   = (const float*)d_in[17];
    float* out = (float*)d_out;

    float *T, *h0, *h1, *h2, *wp, *dinv;
    int *ib, *col;
    cudaGetSymbolAddress((void**)&T,    g_T);
    cudaGetSymbolAddress((void**)&h0,   g_h0);
    cudaGetSymbolAddress((void**)&h1,   g_h1);
    cudaGetSymbolAddress((void**)&h2,   g_h2);
    cudaGetSymbolAddress((void**)&wp,   g_wp);
    cudaGetSymbolAddress((void**)&col,  g_col);
    cudaGetSymbolAddress((void**)&ib,   g_int);
    cudaGetSymbolAddress((void**)&dinv, g_dinv);

    int* degs = ib;
    int* degd = ib + N_TOT;
    int* rs   = ib + 2 * N_TOT;
    int* cur  = ib + 3 * N_TOT;
    int* ctr  = ib + 4 * N_TOT;

    // Graph descriptors over concatenated edge space
    GDesc gC0 = { ei0, ei0 + EE0, nullptr, 0,                          EE0,  NB_C0, 1 };
    GDesc gC1 = { ei1, ei1 + EE1, nullptr, EE0,                        EE1,  NB_C1, 1 };
    GDesc gC2 = { ei2, ei2 + EE2, nullptr, EE0 + EE1,                  EE2,  NB_C2, 1 };
    GDesc gP0 = { D0c, D0r,       D0v,     EE0 + EE1 + EE2,            E_P0, NB_P0, 0 };
    GDesc gP1 = { D1c, D1r,       D1v,     EE0 + EE1 + EE2 + E_P0,     E_P1, NB_P1, 0 };

    // ---- Batched CSR build for ALL 5 graphs: 4 launches total ----
    zero_build_kernel<<<cdiv(2 * N_TOT, 256), 256>>>(ib);
    hist_all_kernel<<<cdiv(E_TOT, 256), 256>>>(gC0, gC1, gC2, gP0, gP1, degs, degd);
    rowstart_all_kernel<<<cdiv(N_TOT, 256), 256>>>(degd, degs, rs, cur, ctr, dinv);
    scatter_all_kernel<<<cdiv(E_TOT, 256), 256>>>(gC0, gC1, gC2, gP0, gP1, dinv, cur, col, wp);

    // ---- Level 0: ChebConv(3 -> 128) on N0; T layout [N0][24] ----
    copy4_kernel<<<cdiv(NN0, 256), 256>>>(x, T, NN0);
    gather3_kernel<<<cdiv(NN0, 256), 256>>>(rs + NB_C0, degd + NB_C0, col, wp,
                                            T, T + 4, nullptr, NN0);
    for (int k = 2; k < KCH; k++) {
        gather3_kernel<<<cdiv(NN0, 256), 256>>>(rs + NB_C0, degd + NB_C0, col, wp,
                                                T + (k - 1) * 4, T + k * 4, T + (k - 2) * 4, NN0);
    }
    level0_out_kernel<<<cdiv(NN0, 2), 256>>>(T, W0, b0, h0, NN0);

    // ---- Pool 0 (fused ReLU): h0 [N0,128] -> T0 slot of level-1 T [N1,768] ----
    gather128_kernel<<<cdiv(NN1 * 32, 256), 256>>>(rs + NB_P0, degd + NB_P0, col, wp,
                                                   h0, 128, T, 768, nullptr, 768, 1, NN1);

    // ---- Level 1: ChebConv(128 -> 128) on N1 ----
    {
        const int st = 768;
        int thr = NN1 * 32;
        gather128_kernel<<<cdiv(thr, 256), 256>>>(rs + NB_C1, degd + NB_C1, col, wp,
                                                  T, st, T + 128, st, nullptr, st, 0, NN1);
        for (int k = 2; k < KCH; k++) {
            gather128_kernel<<<cdiv(thr, 256), 256>>>(rs + NB_C1, degd + NB_C1, col, wp,
                                                      T + (size_t)(k - 1) * 128, st,
                                                      T + (size_t)k * 128, st,
                                                      T + (size_t)(k - 2) * 128, st, 0, NN1);
        }
        dim3 grid(128 / 64, cdiv(NN1, 128));
        gemm_bias_tc_kernel<<<grid, 256>>>(T, W1, b1, h1, NN1, 128, st);
    }

    // ---- Pool 1 (fused ReLU): h1 [N1,128] -> T0 slot of level-2 T [N2,768] ----
    gather128_kernel<<<cdiv(NN2 * 32, 256), 256>>>(rs + NB_P1, degd + NB_P1, col, wp,
                                                   h1, 128, T, 768, nullptr, 768, 1, NN2);

    // ---- Level 2: ChebConv(128 -> 256) on N2 (no relu) ----
    {
        const int st = 768;
        int thr = NN2 * 32;
        gather128_kernel<<<cdiv(thr, 256), 256>>>(rs + NB_C2, degd + NB_C2, col, wp,
                                                  T, st, T + 128, st, nullptr, st, 0, NN2);
        for (int k = 2; k < KCH; k++) {
            gather128_kernel<<<cdiv(thr, 256), 256>>>(rs + NB_C2, degd + NB_C2, col, wp,
                                                      T + (size_t)(k - 1) * 128, st,
                                                      T + (size_t)k * 128, st,
                                                      T + (size_t)(k - 2) * 128, st, 0, NN2);
        }
        dim3 grid(256 / 64, cdiv(NN2, 128));
        gemm_bias_tc_kernel<<<grid, 256>>>(T, W2, b2, h2, NN2, 256, st);
    }

    // ---- Final: Z = linW @ vec(h2) + linb ----
    init_out_kernel<<<1, 32>>>(linb, out);
    final_kernel<<<1024, 256>>>(linW, h2, out);
}